// round 6
// baseline (speedup 1.0000x reference)
#include <cuda_runtime.h>
#include <math.h>
#include <stdint.h>

// ---------------- problem constants ----------------
#define T_TOK 4096
#define S_LEN 2048
#define DIMM 1024
#define QC 128
#define KVC 128
#define KROPE 64
#define VHD 256
#define HD 128

// ---------------- scratch ----------------
__device__ float g_dq[T_TOK * QC];
__device__ float g_dkv[T_TOK * (KVC + KROPE)];
__device__ float g_cq[T_TOK * QC];
__device__ float g_ckv[T_TOK * KVC];
__device__ float g_krope[T_TOK * KROPE];
__device__ float g_qraw[(size_t)T_TOK * 1024];
__device__ float g_kvraw[(size_t)T_TOK * 2560];
__device__ float g_q[(size_t)16 * S_LEN * HD];     // [bh][s][128] tf32
__device__ float g_k[(size_t)16 * S_LEN * HD];     // [bh][s][128] tf32
__device__ float g_vt[(size_t)16 * VHD * S_LEN];   // [bh][n][s]  tf32 (V^T)
__device__ float g_attn[(size_t)T_TOK * 2048];

// ---------------- helpers ----------------
__device__ __forceinline__ float f2tf(float f) {
    uint32_t u;
    asm("cvt.rna.tf32.f32 %0, %1;" : "=r"(u) : "f"(f));
    return __uint_as_float(u);
}

__device__ __forceinline__ void mma_tf32(float c[4], const uint32_t a[4], const uint32_t b[2]) {
    asm volatile(
        "mma.sync.aligned.m16n8k8.row.col.f32.tf32.tf32.f32 "
        "{%0,%1,%2,%3},{%4,%5,%6,%7},{%8,%9},{%0,%1,%2,%3};"
        : "+f"(c[0]), "+f"(c[1]), "+f"(c[2]), "+f"(c[3])
        : "r"(a[0]), "r"(a[1]), "r"(a[2]), "r"(a[3]), "r"(b[0]), "r"(b[1]));
}

__device__ __forceinline__ void ldsm4(uint32_t r[4], uint32_t saddr) {
    asm volatile("ldmatrix.sync.aligned.m8n8.x4.shared.b16 {%0,%1,%2,%3}, [%4];"
        : "=r"(r[0]), "=r"(r[1]), "=r"(r[2]), "=r"(r[3]) : "r"(saddr));
}

__device__ __forceinline__ void cp_async16(void* smem_dst, const void* gsrc) {
    uint32_t s = (uint32_t)__cvta_generic_to_shared(smem_dst);
    asm volatile("cp.async.ca.shared.global [%0], [%1], 16;\n" :: "r"(s), "l"(gsrc));
}
#define CP_COMMIT() asm volatile("cp.async.commit_group;\n" ::: "memory")
#define CP_WAIT1()  asm volatile("cp.async.wait_group 1;\n" ::: "memory")
#define CP_WAIT0()  asm volatile("cp.async.wait_group 0;\n" ::: "memory")
#define BAR_PAIR(id) asm volatile("bar.sync %0, 64;" :: "r"(id) : "memory")

// ---------------- double-buffered tf32 tensor-core GEMM (unchanged) ----------------
template<int BN>
__global__ __launch_bounds__(256) void sgemm_db(
    const float* __restrict__ A, const float* __restrict__ W,
    const float* __restrict__ bias, float* __restrict__ C,
    int M, int N, int K)
{
    constexpr int BM = 128, BK = 16;
    constexpr int LDA = BK + 4;
    constexpr int LDB = BN + 8;
    constexpr int NJ = BN / 16;
    constexpr int RB = BN / 64;
    __shared__ float As[2][BM][LDA];
    __shared__ float Bs[2][BK][LDB];

    int tid = threadIdx.x, lane = tid & 31, w = tid >> 5;
    int g = lane >> 2, t = lane & 3;
    int wm = (w >> 1) * 32, wn = (w & 1) * (BN / 2);
    int m0 = blockIdx.y * BM, n0 = blockIdx.x * BN;

    int ar = tid >> 1, ac = (tid & 1) * 8;
    int br = tid >> 4, bc = (tid & 15) * (4 * RB);

    const float* Ag = A + (size_t)(m0 + ar) * K + ac;
    const float* Wg = W + (size_t)br * N + n0 + bc;

    float c[2][NJ][4] = {};
    float4 ra0, ra1, rb[RB];

    auto gload = [&](int k0) {
        ra0 = *(const float4*)(Ag + k0);
        ra1 = *(const float4*)(Ag + k0 + 4);
        #pragma unroll
        for (int r = 0; r < RB; r++)
            rb[r] = *(const float4*)(Wg + (size_t)k0 * N + r * 4);
    };
    auto sstore = [&](int buf) {
        As[buf][ar][ac + 0] = f2tf(ra0.x); As[buf][ar][ac + 1] = f2tf(ra0.y);
        As[buf][ar][ac + 2] = f2tf(ra0.z); As[buf][ar][ac + 3] = f2tf(ra0.w);
        As[buf][ar][ac + 4] = f2tf(ra1.x); As[buf][ar][ac + 5] = f2tf(ra1.y);
        As[buf][ar][ac + 6] = f2tf(ra1.z); As[buf][ar][ac + 7] = f2tf(ra1.w);
        #pragma unroll
        for (int r = 0; r < RB; r++) {
            Bs[buf][br][bc + r * 4 + 0] = f2tf(rb[r].x);
            Bs[buf][br][bc + r * 4 + 1] = f2tf(rb[r].y);
            Bs[buf][br][bc + r * 4 + 2] = f2tf(rb[r].z);
            Bs[buf][br][bc + r * 4 + 3] = f2tf(rb[r].w);
        }
    };

    gload(0);
    sstore(0);
    __syncthreads();

    int nt = K / BK;
    for (int it = 0; it < nt; it++) {
        int cur = it & 1;
        if (it + 1 < nt) gload((it + 1) * BK);
        #pragma unroll
        for (int ks = 0; ks < 16; ks += 8) {
            uint32_t a[2][4], b[NJ][2];
            #pragma unroll
            for (int i = 0; i < 2; i++) {
                int mr = wm + i * 16;
                a[i][0] = __float_as_uint(As[cur][mr + g][ks + t]);
                a[i][1] = __float_as_uint(As[cur][mr + g + 8][ks + t]);
                a[i][2] = __float_as_uint(As[cur][mr + g][ks + t + 4]);
                a[i][3] = __float_as_uint(As[cur][mr + g + 8][ks + t + 4]);
            }
            #pragma unroll
            for (int j = 0; j < NJ; j++) {
                b[j][0] = __float_as_uint(Bs[cur][ks + t][wn + j * 8 + g]);
                b[j][1] = __float_as_uint(Bs[cur][ks + t + 4][wn + j * 8 + g]);
            }
            #pragma unroll
            for (int i = 0; i < 2; i++)
                #pragma unroll
                for (int j = 0; j < NJ; j++)
                    mma_tf32(c[i][j], a[i], b[j]);
        }
        if (it + 1 < nt) sstore(cur ^ 1);
        __syncthreads();
    }

    #pragma unroll
    for (int i = 0; i < 2; i++) {
        #pragma unroll
        for (int j = 0; j < NJ; j++) {
            int row = m0 + wm + i * 16 + g;
            int col = n0 + wn + j * 8 + 2 * t;
            float2 bb = *(const float2*)&bias[col];
            float2 o0 = { c[i][j][0] + bb.x, c[i][j][1] + bb.y };
            float2 o1 = { c[i][j][2] + bb.x, c[i][j][3] + bb.y };
            *(float2*)&C[(size_t)row * N + col] = o0;
            *(float2*)&C[(size_t)(row + 8) * N + col] = o1;
        }
    }
}

// ---------------- fused RMSNorm + K-rope ----------------
__global__ __launch_bounds__(128) void norm_rope_kernel(
    const float* __restrict__ dq, const float* __restrict__ dkv,
    const float* __restrict__ qnw, const float* __restrict__ kvnw,
    const int* __restrict__ pos_ids,
    float* __restrict__ cq, float* __restrict__ ckv, float* __restrict__ kr)
{
    int t = blockIdx.x, tid = threadIdx.x;
    int lane = tid & 31, wid = tid >> 5;
    __shared__ float r1[4], r2[4];
    float v1 = dq[t * 128 + tid];
    float v2 = dkv[t * 192 + tid];
    float s1 = v1 * v1, s2 = v2 * v2;
    #pragma unroll
    for (int o = 16; o; o >>= 1) {
        s1 += __shfl_xor_sync(0xffffffffu, s1, o);
        s2 += __shfl_xor_sync(0xffffffffu, s2, o);
    }
    if (!lane) { r1[wid] = s1; r2[wid] = s2; }
    __syncthreads();
    float t1 = r1[0] + r1[1] + r1[2] + r1[3];
    float t2 = r2[0] + r2[1] + r2[2] + r2[3];
    cq[t * 128 + tid]  = qnw[tid]  * v1 * rsqrtf(t1 * (1.0f / 128.0f) + 1e-8f);
    ckv[t * 128 + tid] = kvnw[tid] * v2 * rsqrtf(t2 * (1.0f / 128.0f) + 1e-8f);
    if (tid < 64) {
        int p = pos_ids[t];
        int i = tid >> 1;
        float invf = (float)exp(-(double)(2 * i) / 64.0 * log(10000.0));
        float ang = (float)p * invf;
        float sn, cs; sincosf(ang, &sn, &cs);
        float xe = dkv[t * 192 + 128 + 2 * i];
        float xo = dkv[t * 192 + 128 + 2 * i + 1];
        kr[t * 64 + tid] = (tid & 1) ? (xe * sn + xo * cs) : (xe * cs - xo * sn);
    }
}

// ---------------- scatter Q/K (tf32-converted) ----------------
__global__ __launch_bounds__(256) void scatter_qk(
    const float* __restrict__ qraw, const float* __restrict__ kvraw,
    const float* __restrict__ kr, const int* __restrict__ pos_ids,
    float* __restrict__ gq, float* __restrict__ gk)
{
    int t = blockIdx.x;
    int b = t >> 11, s = t & 2047;
    int tid = threadIdx.x;
    int p = pos_ids[t];
    const float* qrow = qraw + (size_t)t * 1024;
    const float* kvrow = kvraw + (size_t)t * 2560;
    for (int h = 0; h < 8; h++) {
        size_t qk_base = ((size_t)(b * 8 + h) * 2048 + s) * 128;
        if (tid < 128) {
            int d = tid;
            float val;
            if (d < 96) {
                val = qrow[h * 96 + d];
            } else {
                int j = d - 96, i = j >> 1;
                float invf = (float)exp(-(double)(2 * i) / 32.0 * log(10000.0));
                float ang = (float)p * invf;
                float sn, cs; sincosf(ang, &sn, &cs);
                const float* rb = qrow + 768 + h * 32;
                float xe = rb[2 * i], xo = rb[2 * i + 1];
                val = (j & 1) ? (xe * sn + xo * cs) : (xe * cs - xo * sn);
            }
            gq[qk_base + d] = f2tf(val);
        } else {
            int d = tid - 128;
            float val = (d < 64) ? kvrow[h * 64 + d] : kr[t * 64 + (d - 64)];
            gk[qk_base + d] = f2tf(val);
        }
    }
}

// ---------------- V transpose: kvraw V part -> gvt[bh][n][s] (tf32) ----------------
__global__ __launch_bounds__(256) void v_transpose(
    const float* __restrict__ kvraw, float* __restrict__ gvt)
{
    __shared__ float ts[32][33];
    int bh = blockIdx.x;
    int s0 = blockIdx.y * 32, n0 = blockIdx.z * 32;
    int b = bh >> 3, h = bh & 7;
    int c = threadIdx.x & 31, r0 = threadIdx.x >> 5;
    #pragma unroll
    for (int rr = r0; rr < 32; rr += 8)
        ts[rr][c] = kvraw[(size_t)(b * 2048 + s0 + rr) * 2560 + 512 + h * 256 + n0 + c];
    __syncthreads();
    #pragma unroll
    for (int rr = r0; rr < 32; rr += 8)
        gvt[(size_t)(bh * 256 + n0 + rr) * 2048 + s0 + c] = f2tf(ts[c][rr]);
}

// ---------------- flash attention: warp-pair row ownership, in-register softmax ----
// BQ=128, BK=64, d=128, v=256, 512 threads (16 warps).
// scores: warps (8m,2n) tile 16x32; PV: warps (8m,2n) tile 16x128.
#define FQ_F (128 * 132)
#define FK_F (64 * 132)
#define FV_F (256 * 68)
#define FS_F (128 * 68)
#define FA4_FLOATS (FQ_F + FK_F + FV_F + FS_F + 512)
#define FA4_BYTES  (FA4_FLOATS * 4)

__global__ __launch_bounds__(512, 1) void flash_tc(
    const float* __restrict__ Q, const float* __restrict__ K,
    const float* __restrict__ VT, float* __restrict__ O)
{
    extern __shared__ __align__(16) float sm[];
    float* Qs = sm;                 // [128][132] tf32
    float* Ks = Qs + FQ_F;          // [64][132]  tf32
    float* Vs = Ks + FK_F;          // [256][68]  tf32 (V^T [n][k])
    float* Ss = Vs + FV_F;          // [128][68]  tf32 P
    float* exM = Ss + FS_F;         // [16][16] pair max exchange
    float* exL = exM + 256;         // [16][16] pair sum exchange

    int bh = blockIdx.y, q0 = blockIdx.x * 128;
    const float* Qg = Q + ((size_t)bh * 2048 + q0) * 128;
    const float* Kg = K + (size_t)bh * 2048 * 128;
    const float* Vg = VT + (size_t)bh * 256 * 2048;
    int tid = threadIdx.x, lane = tid & 31, w = tid >> 5;
    int g = lane >> 2, t = lane & 3;

    int wm = (w >> 1) * 16;          // 8 m-groups of 16 rows
    int wns = (w & 1) * 32;          // score n-half
    int pvn = (w & 1) * 128;         // pv n-half
    int pid = (w >> 1) + 1;          // named barrier id 1..8
    int wp = w ^ 1;                  // pair partner

    int laneA_row = ((lane >> 3) & 1) * 8 + (lane & 7);
    int laneA_col = (lane >> 4) * 4;
    int laneB_row = (lane >> 4) * 8 + (lane & 7);
    int laneB_col = ((lane >> 3) & 1) * 4;

    uint32_t qA = (uint32_t)__cvta_generic_to_shared(
        &Qs[(wm + laneA_row) * 132 + laneA_col]);
    uint32_t kB = (uint32_t)__cvta_generic_to_shared(
        &Ks[(wns + laneB_row) * 132 + laneB_col]);
    uint32_t pA = (uint32_t)__cvta_generic_to_shared(
        &Ss[(wm + laneA_row) * 68 + laneA_col]);
    uint32_t vB = (uint32_t)__cvta_generic_to_shared(
        &Vs[laneB_row * 68 + laneB_col]);

    auto loadK = [&](int kc) {
        const float* Kc = Kg + (size_t)kc * 64 * 128;
        #pragma unroll
        for (int i = tid; i < 2048; i += 512) {
            int r = i >> 5, c = (i & 31) << 2;
            cp_async16(&Ks[r * 132 + c], &Kc[r * 128 + c]);
        }
    };
    auto loadV = [&](int kc) {
        #pragma unroll
        for (int i = tid; i < 4096; i += 512) {
            int r = i >> 4, c = (i & 15) << 2;
            cp_async16(&Vs[r * 68 + c], &Vg[(size_t)r * 2048 + kc * 64 + c]);
        }
    };

    // prologue
    for (int i = tid; i < 4096; i += 512) {
        int r = i >> 5, c = (i & 31) << 2;
        *(float4*)&Qs[r * 132 + c] = *(const float4*)&Qg[r * 128 + c];
    }
    loadK(0); CP_COMMIT();
    loadV(0); CP_COMMIT();

    float m0 = -1e30f, m1 = -1e30f, l0 = 0.f, l1 = 0.f;
    float oc[16][4] = {};
    const float scale = 0.08838834764831845f;  // 1/sqrt(128)

    for (int kc = 0; kc < 32; kc++) {
        CP_WAIT1();               // K(kc) landed (V(kc) may be in flight)
        __syncthreads();

        // ---- scores: warp tile 16m x 32n ----
        float sc[4][4] = {};
        #pragma unroll 4
        for (int d = 0; d < 128; d += 8) {
            uint32_t a[4], b0[4], b1[4];
            ldsm4(a, qA + d * 4);
            ldsm4(b0, kB + d * 4);
            ldsm4(b1, kB + (16 * 132 + d) * 4);
            mma_tf32(sc[0], a, &b0[0]); mma_tf32(sc[1], a, &b0[2]);
            mma_tf32(sc[2], a, &b1[0]); mma_tf32(sc[3], a, &b1[2]);
        }
        #pragma unroll
        for (int j = 0; j < 4; j++) {
            sc[j][0] *= scale; sc[j][1] *= scale;
            sc[j][2] *= scale; sc[j][3] *= scale;
        }

        // ---- in-register softmax (rows wm+g and wm+g+8) ----
        float mc0 = fmaxf(fmaxf(sc[0][0], sc[0][1]), fmaxf(sc[1][0], sc[1][1]));
        mc0 = fmaxf(mc0, fmaxf(fmaxf(sc[2][0], sc[2][1]), fmaxf(sc[3][0], sc[3][1])));
        float mc1 = fmaxf(fmaxf(sc[0][2], sc[0][3]), fmaxf(sc[1][2], sc[1][3]));
        mc1 = fmaxf(mc1, fmaxf(fmaxf(sc[2][2], sc[2][3]), fmaxf(sc[3][2], sc[3][3])));
        mc0 = fmaxf(mc0, __shfl_xor_sync(0xffffffffu, mc0, 1));
        mc0 = fmaxf(mc0, __shfl_xor_sync(0xffffffffu, mc0, 2));
        mc1 = fmaxf(mc1, __shfl_xor_sync(0xffffffffu, mc1, 1));
        mc1 = fmaxf(mc1, __shfl_xor_sync(0xffffffffu, mc1, 2));
        if (t == 0) { exM[w * 16 + g] = mc0; exM[w * 16 + 8 + g] = mc1; }
        BAR_PAIR(pid);
        mc0 = fmaxf(mc0, exM[wp * 16 + g]);
        mc1 = fmaxf(mc1, exM[wp * 16 + 8 + g]);
        float mn0 = fmaxf(m0, mc0), mn1 = fmaxf(m1, mc1);
        float al0 = __expf(m0 - mn0), al1 = __expf(m1 - mn1);
        m0 = mn0; m1 = mn1;

        float ls0 = 0.f, ls1 = 0.f;
        float* pr0 = &Ss[(wm + g) * 68 + wns + 2 * t];
        float* pr1 = &Ss[(wm + g + 8) * 68 + wns + 2 * t];
        #pragma unroll
        for (int j = 0; j < 4; j++) {
            float p00 = __expf(sc[j][0] - mn0), p01 = __expf(sc[j][1] - mn0);
            float p10 = __expf(sc[j][2] - mn1), p11 = __expf(sc[j][3] - mn1);
            ls0 += p00 + p01; ls1 += p10 + p11;
            float2 v0 = { f2tf(p00), f2tf(p01) };
            float2 v1 = { f2tf(p10), f2tf(p11) };
            *(float2*)&pr0[j * 8] = v0;
            *(float2*)&pr1[j * 8] = v1;
        }
        ls0 += __shfl_xor_sync(0xffffffffu, ls0, 1);
        ls0 += __shfl_xor_sync(0xffffffffu, ls0, 2);
        ls1 += __shfl_xor_sync(0xffffffffu, ls1, 1);
        ls1 += __shfl_xor_sync(0xffffffffu, ls1, 2);
        if (t == 0) { exL[w * 16 + g] = ls0; exL[w * 16 + 8 + g] = ls1; }
        BAR_PAIR(pid);                       // also makes pair's P visible
        ls0 += exL[wp * 16 + g];
        ls1 += exL[wp * 16 + 8 + g];
        l0 = l0 * al0 + ls0;
        l1 = l1 * al1 + ls1;

        CP_WAIT0();               // V(kc) landed
        __syncthreads();          // V visible to all; Ks free
        if (kc + 1 < 32) loadK(kc + 1);
        CP_COMMIT();              // K(kc+1) streams during PV

        // ---- PV: O += P @ V (warp tile 16m x 128n) ----
        #pragma unroll
        for (int nt = 0; nt < 16; nt++) {
            oc[nt][0] *= al0; oc[nt][1] *= al0;
            oc[nt][2] *= al1; oc[nt][3] *= al1;
        }
        #pragma unroll
        for (int ks = 0; ks < 64; ks += 8) {
            uint32_t a[4];
            ldsm4(a, pA + ks * 4);
            #pragma unroll
            for (int nt = 0; nt < 8; nt++) {
                uint32_t bb[4];
                ldsm4(bb, vB + (((pvn + nt * 16) * 68) + ks) * 4);
                mma_tf32(oc[nt * 2],     a, &bb[0]);
                mma_tf32(oc[nt * 2 + 1], a, &bb[2]);
            }
        }
        __syncthreads();          // Vs free
        if (kc + 1 < 32) loadV(kc + 1);
        CP_COMMIT();              // V(kc+1) streams during next scores
    }

    // epilogue
    int b = bh >> 3, h = bh & 7;
    float inv0 = 1.0f / l0, inv1 = 1.0f / l1;
    int row0 = q0 + wm + g, row1 = row0 + 8;
    #pragma unroll
    for (int nt = 0; nt < 16; nt++) {
        int col = h * 256 + pvn + nt * 8 + 2 * t;
        float2 o0 = { oc[nt][0] * inv0, oc[nt][1] * inv0 };
        float2 o1 = { oc[nt][2] * inv1, oc[nt][3] * inv1 };
        *(float2*)&O[((size_t)(b * 2048 + row0)) * 2048 + col] = o0;
        *(float2*)&O[((size_t)(b * 2048 + row1)) * 2048 + col] = o1;
    }
}

// ---------------- launch ----------------
extern "C" void kernel_launch(void* const* d_in, const int* in_sizes, int n_in,
                              void* d_out, int out_size)
{
    const float* x         = (const float*)d_in[0];
    const int*   pos       = (const int*)d_in[1];
    const float* w_dq_w    = (const float*)d_in[2];
    const float* w_dq_b    = (const float*)d_in[3];
    const float* q_norm_w  = (const float*)d_in[4];
    const float* w_uq_qr_w = (const float*)d_in[5];
    const float* w_uq_qr_b = (const float*)d_in[6];
    const float* w_dkv_w   = (const float*)d_in[7];
    const float* w_dkv_b   = (const float*)d_in[8];
    const float* kv_norm_w = (const float*)d_in[9];
    const float* w_uk_w    = (const float*)d_in[10];
    const float* w_uk_b    = (const float*)d_in[11];
    const float* w_o_w     = (const float*)d_in[12];
    const float* w_o_b     = (const float*)d_in[13];
    float* out = (float*)d_out;

    float *dq, *dkv, *cq, *ckv, *kr, *qraw, *kvraw, *gq, *gk, *gvt, *gattn;
    cudaGetSymbolAddress((void**)&dq, g_dq);
    cudaGetSymbolAddress((void**)&dkv, g_dkv);
    cudaGetSymbolAddress((void**)&cq, g_cq);
    cudaGetSymbolAddress((void**)&ckv, g_ckv);
    cudaGetSymbolAddress((void**)&kr, g_krope);
    cudaGetSymbolAddress((void**)&qraw, g_qraw);
    cudaGetSymbolAddress((void**)&kvraw, g_kvraw);
    cudaGetSymbolAddress((void**)&gq, g_q);
    cudaGetSymbolAddress((void**)&gk, g_k);
    cudaGetSymbolAddress((void**)&gvt, g_vt);
    cudaGetSymbolAddress((void**)&gattn, g_attn);

    cudaFuncSetAttribute(flash_tc, cudaFuncAttributeMaxDynamicSharedMemorySize,
                         FA4_BYTES);

    // down projections
    sgemm_db<128><<<dim3(1, 32), 256>>>(x, w_dq_w, w_dq_b, dq, T_TOK, QC, DIMM);
    sgemm_db<64><<<dim3(3, 32), 256>>>(x, w_dkv_w, w_dkv_b, dkv,
                                       T_TOK, KVC + KROPE, DIMM);
    // rmsnorm + k rope
    norm_rope_kernel<<<T_TOK, 128>>>(dq, dkv, q_norm_w, kv_norm_w, pos, cq, ckv, kr);
    // up projections
    sgemm_db<128><<<dim3(8, 32), 256>>>(cq, w_uq_qr_w, w_uq_qr_b, qraw,
                                        T_TOK, 1024, QC);
    sgemm_db<128><<<dim3(20, 32), 256>>>(ckv, w_uk_w, w_uk_b, kvraw,
                                         T_TOK, 2560, KVC);
    // build per-head states
    scatter_qk<<<T_TOK, 256>>>(qraw, kvraw, kr, pos, gq, gk);
    v_transpose<<<dim3(16, 64, 8), 256>>>(kvraw, gvt);
    // attention
    flash_tc<<<dim3(S_LEN / 128, 16), 512, FA4_BYTES>>>(gq, gk, gvt, gattn);
    // output projection
    sgemm_db<128><<<dim3(8, 32), 256>>>(gattn, w_o_w, w_o_b, out,
                                        T_TOK, DIMM, 2048);
}

// round 8
// speedup vs baseline: 2.1482x; 2.1482x over previous
#include <cuda_runtime.h>
#include <cuda_fp16.h>
#include <math.h>
#include <stdint.h>

// ---------------- problem constants ----------------
#define T_TOK 4096
#define S_LEN 2048
#define DIMM 1024
#define QC 128
#define KVC 128
#define KROPE 64
#define VHD 256
#define HD 128

// ---------------- scratch ----------------
__device__ float g_dq[T_TOK * QC];
__device__ float g_dkv[T_TOK * (KVC + KROPE)];
__device__ float g_cq[T_TOK * QC];
__device__ float g_ckv[T_TOK * KVC];
__device__ float g_krope[T_TOK * KROPE];
__device__ float g_qraw[(size_t)T_TOK * 1024];
__device__ float g_kvraw[(size_t)T_TOK * 2560];
__device__ __half g_qh[(size_t)16 * S_LEN * HD];    // [bh][s][128] fp16
__device__ __half g_kh[(size_t)16 * S_LEN * HD];    // [bh][s][128] fp16
__device__ __half g_vth[(size_t)16 * VHD * S_LEN];  // [bh][n][s]  fp16 (V^T)
__device__ float g_attn[(size_t)T_TOK * 2048];

// ---------------- helpers ----------------
__device__ __forceinline__ float f2tf(float f) {
    uint32_t u;
    asm("cvt.rna.tf32.f32 %0, %1;" : "=r"(u) : "f"(f));
    return __uint_as_float(u);
}

__device__ __forceinline__ void mma_tf32(float c[4], const uint32_t a[4], const uint32_t b[2]) {
    asm volatile(
        "mma.sync.aligned.m16n8k8.row.col.f32.tf32.tf32.f32 "
        "{%0,%1,%2,%3},{%4,%5,%6,%7},{%8,%9},{%0,%1,%2,%3};"
        : "+f"(c[0]), "+f"(c[1]), "+f"(c[2]), "+f"(c[3])
        : "r"(a[0]), "r"(a[1]), "r"(a[2]), "r"(a[3]), "r"(b[0]), "r"(b[1]));
}

__device__ __forceinline__ void mma_f16(float c[4], const uint32_t a[4], const uint32_t b[2]) {
    asm volatile(
        "mma.sync.aligned.m16n8k16.row.col.f32.f16.f16.f32 "
        "{%0,%1,%2,%3},{%4,%5,%6,%7},{%8,%9},{%0,%1,%2,%3};"
        : "+f"(c[0]), "+f"(c[1]), "+f"(c[2]), "+f"(c[3])
        : "r"(a[0]), "r"(a[1]), "r"(a[2]), "r"(a[3]), "r"(b[0]), "r"(b[1]));
}

__device__ __forceinline__ void ldsm4(uint32_t r[4], uint32_t saddr) {
    asm volatile("ldmatrix.sync.aligned.m8n8.x4.shared.b16 {%0,%1,%2,%3}, [%4];"
        : "=r"(r[0]), "=r"(r[1]), "=r"(r[2]), "=r"(r[3]) : "r"(saddr));
}

__device__ __forceinline__ void cp_async16(void* smem_dst, const void* gsrc) {
    uint32_t s = (uint32_t)__cvta_generic_to_shared(smem_dst);
    asm volatile("cp.async.ca.shared.global [%0], [%1], 16;\n" :: "r"(s), "l"(gsrc));
}
#define CP_COMMIT() asm volatile("cp.async.commit_group;\n" ::: "memory")
#define CP_WAIT1()  asm volatile("cp.async.wait_group 1;\n" ::: "memory")

__device__ __forceinline__ uint32_t packh2(float lo, float hi) {
    __half2 h = __floats2half2_rn(lo, hi);
    return *(uint32_t*)&h;
}

// ---------------- double-buffered tf32 tensor-core GEMM (unchanged) ----------------
template<int BN>
__global__ __launch_bounds__(256) void sgemm_db(
    const float* __restrict__ A, const float* __restrict__ W,
    const float* __restrict__ bias, float* __restrict__ C,
    int M, int N, int K)
{
    constexpr int BM = 128, BK = 16;
    constexpr int LDA = BK + 4;
    constexpr int LDB = BN + 8;
    constexpr int NJ = BN / 16;
    constexpr int RB = BN / 64;
    __shared__ float As[2][BM][LDA];
    __shared__ float Bs[2][BK][LDB];

    int tid = threadIdx.x, lane = tid & 31, w = tid >> 5;
    int g = lane >> 2, t = lane & 3;
    int wm = (w >> 1) * 32, wn = (w & 1) * (BN / 2);
    int m0 = blockIdx.y * BM, n0 = blockIdx.x * BN;

    int ar = tid >> 1, ac = (tid & 1) * 8;
    int br = tid >> 4, bc = (tid & 15) * (4 * RB);

    const float* Ag = A + (size_t)(m0 + ar) * K + ac;
    const float* Wg = W + (size_t)br * N + n0 + bc;

    float c[2][NJ][4] = {};
    float4 ra0, ra1, rb[RB];

    auto gload = [&](int k0) {
        ra0 = *(const float4*)(Ag + k0);
        ra1 = *(const float4*)(Ag + k0 + 4);
        #pragma unroll
        for (int r = 0; r < RB; r++)
            rb[r] = *(const float4*)(Wg + (size_t)k0 * N + r * 4);
    };
    auto sstore = [&](int buf) {
        As[buf][ar][ac + 0] = f2tf(ra0.x); As[buf][ar][ac + 1] = f2tf(ra0.y);
        As[buf][ar][ac + 2] = f2tf(ra0.z); As[buf][ar][ac + 3] = f2tf(ra0.w);
        As[buf][ar][ac + 4] = f2tf(ra1.x); As[buf][ar][ac + 5] = f2tf(ra1.y);
        As[buf][ar][ac + 6] = f2tf(ra1.z); As[buf][ar][ac + 7] = f2tf(ra1.w);
        #pragma unroll
        for (int r = 0; r < RB; r++) {
            Bs[buf][br][bc + r * 4 + 0] = f2tf(rb[r].x);
            Bs[buf][br][bc + r * 4 + 1] = f2tf(rb[r].y);
            Bs[buf][br][bc + r * 4 + 2] = f2tf(rb[r].z);
            Bs[buf][br][bc + r * 4 + 3] = f2tf(rb[r].w);
        }
    };

    gload(0);
    sstore(0);
    __syncthreads();

    int nt = K / BK;
    for (int it = 0; it < nt; it++) {
        int cur = it & 1;
        if (it + 1 < nt) gload((it + 1) * BK);
        #pragma unroll
        for (int ks = 0; ks < 16; ks += 8) {
            uint32_t a[2][4], b[NJ][2];
            #pragma unroll
            for (int i = 0; i < 2; i++) {
                int mr = wm + i * 16;
                a[i][0] = __float_as_uint(As[cur][mr + g][ks + t]);
                a[i][1] = __float_as_uint(As[cur][mr + g + 8][ks + t]);
                a[i][2] = __float_as_uint(As[cur][mr + g][ks + t + 4]);
                a[i][3] = __float_as_uint(As[cur][mr + g + 8][ks + t + 4]);
            }
            #pragma unroll
            for (int j = 0; j < NJ; j++) {
                b[j][0] = __float_as_uint(Bs[cur][ks + t][wn + j * 8 + g]);
                b[j][1] = __float_as_uint(Bs[cur][ks + t + 4][wn + j * 8 + g]);
            }
            #pragma unroll
            for (int i = 0; i < 2; i++)
                #pragma unroll
                for (int j = 0; j < NJ; j++)
                    mma_tf32(c[i][j], a[i], b[j]);
        }
        if (it + 1 < nt) sstore(cur ^ 1);
        __syncthreads();
    }

    #pragma unroll
    for (int i = 0; i < 2; i++) {
        #pragma unroll
        for (int j = 0; j < NJ; j++) {
            int row = m0 + wm + i * 16 + g;
            int col = n0 + wn + j * 8 + 2 * t;
            float2 bb = *(const float2*)&bias[col];
            float2 o0 = { c[i][j][0] + bb.x, c[i][j][1] + bb.y };
            float2 o1 = { c[i][j][2] + bb.x, c[i][j][3] + bb.y };
            *(float2*)&C[(size_t)row * N + col] = o0;
            *(float2*)&C[(size_t)(row + 8) * N + col] = o1;
        }
    }
}

// ---------------- fused RMSNorm + K-rope (unchanged) ----------------
__global__ __launch_bounds__(128) void norm_rope_kernel(
    const float* __restrict__ dq, const float* __restrict__ dkv,
    const float* __restrict__ qnw, const float* __restrict__ kvnw,
    const int* __restrict__ pos_ids,
    float* __restrict__ cq, float* __restrict__ ckv, float* __restrict__ kr)
{
    int t = blockIdx.x, tid = threadIdx.x;
    int lane = tid & 31, wid = tid >> 5;
    __shared__ float r1[4], r2[4];
    float v1 = dq[t * 128 + tid];
    float v2 = dkv[t * 192 + tid];
    float s1 = v1 * v1, s2 = v2 * v2;
    #pragma unroll
    for (int o = 16; o; o >>= 1) {
        s1 += __shfl_xor_sync(0xffffffffu, s1, o);
        s2 += __shfl_xor_sync(0xffffffffu, s2, o);
    }
    if (!lane) { r1[wid] = s1; r2[wid] = s2; }
    __syncthreads();
    float t1 = r1[0] + r1[1] + r1[2] + r1[3];
    float t2 = r2[0] + r2[1] + r2[2] + r2[3];
    cq[t * 128 + tid]  = qnw[tid]  * v1 * rsqrtf(t1 * (1.0f / 128.0f) + 1e-8f);
    ckv[t * 128 + tid] = kvnw[tid] * v2 * rsqrtf(t2 * (1.0f / 128.0f) + 1e-8f);
    if (tid < 64) {
        int p = pos_ids[t];
        int i = tid >> 1;
        float invf = (float)exp(-(double)(2 * i) / 64.0 * log(10000.0));
        float ang = (float)p * invf;
        float sn, cs; sincosf(ang, &sn, &cs);
        float xe = dkv[t * 192 + 128 + 2 * i];
        float xo = dkv[t * 192 + 128 + 2 * i + 1];
        kr[t * 64 + tid] = (tid & 1) ? (xe * sn + xo * cs) : (xe * cs - xo * sn);
    }
}

// ---------------- scatter Q/K -> fp16 ----------------
__global__ __launch_bounds__(256) void scatter_qk(
    const float* __restrict__ qraw, const float* __restrict__ kvraw,
    const float* __restrict__ kr, const int* __restrict__ pos_ids,
    __half* __restrict__ gq, __half* __restrict__ gk)
{
    int t = blockIdx.x;
    int b = t >> 11, s = t & 2047;
    int tid = threadIdx.x;
    int p = pos_ids[t];
    const float* qrow = qraw + (size_t)t * 1024;
    const float* kvrow = kvraw + (size_t)t * 2560;
    for (int h = 0; h < 8; h++) {
        size_t qk_base = ((size_t)(b * 8 + h) * 2048 + s) * 128;
        if (tid < 128) {
            int d = tid;
            float val;
            if (d < 96) {
                val = qrow[h * 96 + d];
            } else {
                int j = d - 96, i = j >> 1;
                float invf = (float)exp(-(double)(2 * i) / 32.0 * log(10000.0));
                float ang = (float)p * invf;
                float sn, cs; sincosf(ang, &sn, &cs);
                const float* rb = qrow + 768 + h * 32;
                float xe = rb[2 * i], xo = rb[2 * i + 1];
                val = (j & 1) ? (xe * sn + xo * cs) : (xe * cs - xo * sn);
            }
            gq[qk_base + d] = __float2half_rn(val);
        } else {
            int d = tid - 128;
            float val = (d < 64) ? kvrow[h * 64 + d] : kr[t * 64 + (d - 64)];
            gk[qk_base + d] = __float2half_rn(val);
        }
    }
}

// ---------------- V transpose -> fp16 [bh][n][s] ----------------
__global__ __launch_bounds__(256) void v_transpose(
    const float* __restrict__ kvraw, __half* __restrict__ gvt)
{
    __shared__ float ts[32][33];
    int bh = blockIdx.x;
    int s0 = blockIdx.y * 32, n0 = blockIdx.z * 32;
    int b = bh >> 3, h = bh & 7;
    int c = threadIdx.x & 31, r0 = threadIdx.x >> 5;
    #pragma unroll
    for (int rr = r0; rr < 32; rr += 8)
        ts[rr][c] = kvraw[(size_t)(b * 2048 + s0 + rr) * 2560 + 512 + h * 256 + n0 + c];
    __syncthreads();
    #pragma unroll
    for (int rr = r0; rr < 32; rr += 8)
        gvt[(size_t)(bh * 256 + n0 + rr) * 2048 + s0 + c] = __float2half_rn(ts[c][rr]);
}

// ---------------- fp16 flash attention: P-in-registers, 8 warps ----------------
// BQ=128, BK=64, d=128, v=256, 256 threads. Each warp owns 16 rows completely.
// K rows carry 128 halves -> stride 136 (the round-7 bug was LK=72).
#define LQ 136
#define LK 136
#define LV 72
#define FQ_H (128 * LQ)
#define FK_H (64 * LK)
#define FV_H (256 * LV)
#define FA5_BYTES ((FQ_H + FK_H + FV_H) * 2 + 256)

__global__ __launch_bounds__(256, 1) void flash_f16(
    const __half* __restrict__ Q, const __half* __restrict__ K,
    const __half* __restrict__ VT, float* __restrict__ O)
{
    extern __shared__ __align__(16) __half smh[];
    __half* Qs = smh;            // [128][136]
    __half* Ks = Qs + FQ_H;      // [64][136]
    __half* Vs = Ks + FK_H;      // [256][72]

    int bh = blockIdx.y, q0 = blockIdx.x * 128;
    const __half* Qg = Q + ((size_t)bh * 2048 + q0) * 128;
    const __half* Kg = K + (size_t)bh * 2048 * 128;
    const __half* Vg = VT + (size_t)bh * 256 * 2048;
    int tid = threadIdx.x, lane = tid & 31, w = tid >> 5;
    int g = lane >> 2, t = lane & 3;
    int wm = w * 16;                 // warp's 16 rows

    // ldmatrix lane address components
    int rowA = (lane & 7) + ((lane >> 3) & 1) * 8;   // A: m rows, k halves
    int colA = (lane >> 4) * 8;
    int rowB = (lane & 7) + ((lane >> 4) & 1) * 8;   // B: n rows, k halves
    int colB = ((lane >> 3) & 1) * 8;

    uint32_t qA = (uint32_t)__cvta_generic_to_shared(&Qs[(wm + rowA) * LQ + colA]);
    uint32_t kB = (uint32_t)__cvta_generic_to_shared(&Ks[rowB * LK + colB]);
    uint32_t vB = (uint32_t)__cvta_generic_to_shared(&Vs[rowB * LV + colB]);

    auto loadK = [&](int kc) {
        const __half* Kc = Kg + (size_t)kc * 64 * 128;
        #pragma unroll
        for (int i = tid; i < 1024; i += 256) {
            int r = i >> 4, c = i & 15;
            cp_async16(&Ks[r * LK + c * 8], &Kc[r * 128 + c * 8]);
        }
    };
    auto loadV = [&](int kc) {
        #pragma unroll
        for (int i = tid; i < 2048; i += 256) {
            int r = i >> 3, c = i & 7;
            cp_async16(&Vs[r * LV + c * 8], &Vg[(size_t)r * 2048 + kc * 64 + c * 8]);
        }
    };

    // prologue: Q -> smem, K0/V0 async
    for (int i = tid; i < 2048; i += 256) {
        int r = i >> 4, c = i & 15;
        *(uint4*)&Qs[r * LQ + c * 8] = *(const uint4*)&Qg[r * 128 + c * 8];
    }
    loadK(0); CP_COMMIT();
    loadV(0); CP_COMMIT();
    __syncthreads();

    // hoist Q fragments (16m x 128k = 8 k-groups)
    uint32_t qf[8][4];
    #pragma unroll
    for (int kg = 0; kg < 8; kg++) ldsm4(qf[kg], qA + kg * 32);

    float m0 = -1e30f, m1 = -1e30f, l0 = 0.f, l1 = 0.f;
    float oc[32][4] = {};
    const float scale = 0.08838834764831845f;  // 1/sqrt(128)

    for (int kc = 0; kc < 32; kc++) {
        CP_WAIT1();                // K(kc) done
        __syncthreads();

        // ---- scores: S[16][64] = Q @ K^T ----
        float sc[8][4] = {};
        #pragma unroll
        for (int kg = 0; kg < 8; kg++) {
            #pragma unroll
            for (int ng = 0; ng < 4; ng++) {
                uint32_t bb[4];
                ldsm4(bb, kB + ng * 16 * LK * 2 + kg * 32);
                mma_f16(sc[2 * ng],     qf[kg], &bb[0]);
                mma_f16(sc[2 * ng + 1], qf[kg], &bb[2]);
            }
        }
        __syncthreads();           // all warps done reading Ks

        // ---- in-register softmax (rows wm+g, wm+g+8) ----
        float mc0 = -1e30f, mc1 = -1e30f;
        #pragma unroll
        for (int j = 0; j < 8; j++) {
            sc[j][0] *= scale; sc[j][1] *= scale;
            sc[j][2] *= scale; sc[j][3] *= scale;
            mc0 = fmaxf(mc0, fmaxf(sc[j][0], sc[j][1]));
            mc1 = fmaxf(mc1, fmaxf(sc[j][2], sc[j][3]));
        }
        mc0 = fmaxf(mc0, __shfl_xor_sync(0xffffffffu, mc0, 1));
        mc0 = fmaxf(mc0, __shfl_xor_sync(0xffffffffu, mc0, 2));
        mc1 = fmaxf(mc1, __shfl_xor_sync(0xffffffffu, mc1, 1));
        mc1 = fmaxf(mc1, __shfl_xor_sync(0xffffffffu, mc1, 2));
        float mn0 = fmaxf(m0, mc0), mn1 = fmaxf(m1, mc1);
        float al0 = __expf(m0 - mn0), al1 = __expf(m1 - mn1);
        m0 = mn0; m1 = mn1;

        uint32_t ph[4][4];         // P as fp16 A-fragments (4 k-groups of 16)
        float ls0 = 0.f, ls1 = 0.f;
        #pragma unroll
        for (int j = 0; j < 8; j++) {
            float e0 = __expf(sc[j][0] - mn0);
            float e1 = __expf(sc[j][1] - mn0);
            float e2 = __expf(sc[j][2] - mn1);
            float e3 = __expf(sc[j][3] - mn1);
            ls0 += e0 + e1; ls1 += e2 + e3;
            int kg = j >> 1, hi = (j & 1) * 2;
            ph[kg][hi]     = packh2(e0, e1);
            ph[kg][hi + 1] = packh2(e2, e3);
        }
        ls0 += __shfl_xor_sync(0xffffffffu, ls0, 1);
        ls0 += __shfl_xor_sync(0xffffffffu, ls0, 2);
        ls1 += __shfl_xor_sync(0xffffffffu, ls1, 1);
        ls1 += __shfl_xor_sync(0xffffffffu, ls1, 2);
        l0 = l0 * al0 + ls0;
        l1 = l1 * al1 + ls1;

        if (kc + 1 < 32) loadK(kc + 1);
        CP_COMMIT();
        CP_WAIT1();                // V(kc) done (committed before K(kc+1))
        __syncthreads();

        // ---- PV: O[16][256] += P @ V ----
        #pragma unroll
        for (int nt = 0; nt < 32; nt++) {
            oc[nt][0] *= al0; oc[nt][1] *= al0;
            oc[nt][2] *= al1; oc[nt][3] *= al1;
        }
        #pragma unroll
        for (int kg = 0; kg < 4; kg++) {
            #pragma unroll
            for (int ng = 0; ng < 16; ng++) {
                uint32_t bb[4];
                ldsm4(bb, vB + ng * 16 * LV * 2 + kg * 32);
                mma_f16(oc[2 * ng],     ph[kg], &bb[0]);
                mma_f16(oc[2 * ng + 1], ph[kg], &bb[2]);
            }
        }
        __syncthreads();           // Vs free
        if (kc + 1 < 32) loadV(kc + 1);
        CP_COMMIT();
    }

    // epilogue
    int b = bh >> 3, h = bh & 7;
    float inv0 = 1.0f / l0, inv1 = 1.0f / l1;
    int row0 = q0 + wm + g, row1 = row0 + 8;
    #pragma unroll
    for (int nt = 0; nt < 32; nt++) {
        int col = h * 256 + nt * 8 + 2 * t;
        float2 o0 = { oc[nt][0] * inv0, oc[nt][1] * inv0 };
        float2 o1 = { oc[nt][2] * inv1, oc[nt][3] * inv1 };
        *(float2*)&O[((size_t)(b * 2048 + row0)) * 2048 + col] = o0;
        *(float2*)&O[((size_t)(b * 2048 + row1)) * 2048 + col] = o1;
    }
}

// ---------------- launch ----------------
extern "C" void kernel_launch(void* const* d_in, const int* in_sizes, int n_in,
                              void* d_out, int out_size)
{
    const float* x         = (const float*)d_in[0];
    const int*   pos       = (const int*)d_in[1];
    const float* w_dq_w    = (const float*)d_in[2];
    const float* w_dq_b    = (const float*)d_in[3];
    const float* q_norm_w  = (const float*)d_in[4];
    const float* w_uq_qr_w = (const float*)d_in[5];
    const float* w_uq_qr_b = (const float*)d_in[6];
    const float* w_dkv_w   = (const float*)d_in[7];
    const float* w_dkv_b   = (const float*)d_in[8];
    const float* kv_norm_w = (const float*)d_in[9];
    const float* w_uk_w    = (const float*)d_in[10];
    const float* w_uk_b    = (const float*)d_in[11];
    const float* w_o_w     = (const float*)d_in[12];
    const float* w_o_b     = (const float*)d_in[13];
    float* out = (float*)d_out;

    float *dq, *dkv, *cq, *ckv, *kr, *qraw, *kvraw, *gattn;
    __half *gq, *gk, *gvt;
    cudaGetSymbolAddress((void**)&dq, g_dq);
    cudaGetSymbolAddress((void**)&dkv, g_dkv);
    cudaGetSymbolAddress((void**)&cq, g_cq);
    cudaGetSymbolAddress((void**)&ckv, g_ckv);
    cudaGetSymbolAddress((void**)&kr, g_krope);
    cudaGetSymbolAddress((void**)&qraw, g_qraw);
    cudaGetSymbolAddress((void**)&kvraw, g_kvraw);
    cudaGetSymbolAddress((void**)&gq, g_qh);
    cudaGetSymbolAddress((void**)&gk, g_kh);
    cudaGetSymbolAddress((void**)&gvt, g_vth);
    cudaGetSymbolAddress((void**)&gattn, g_attn);

    cudaFuncSetAttribute(flash_f16, cudaFuncAttributeMaxDynamicSharedMemorySize,
                         FA5_BYTES);

    // down projections
    sgemm_db<128><<<dim3(1, 32), 256>>>(x, w_dq_w, w_dq_b, dq, T_TOK, QC, DIMM);
    sgemm_db<64><<<dim3(3, 32), 256>>>(x, w_dkv_w, w_dkv_b, dkv,
                                       T_TOK, KVC + KROPE, DIMM);
    // rmsnorm + k rope
    norm_rope_kernel<<<T_TOK, 128>>>(dq, dkv, q_norm_w, kv_norm_w, pos, cq, ckv, kr);
    // up projections
    sgemm_db<128><<<dim3(8, 32), 256>>>(cq, w_uq_qr_w, w_uq_qr_b, qraw,
                                        T_TOK, 1024, QC);
    sgemm_db<128><<<dim3(20, 32), 256>>>(ckv, w_uk_w, w_uk_b, kvraw,
                                         T_TOK, 2560, KVC);
    // build per-head states (fp16)
    scatter_qk<<<T_TOK, 256>>>(qraw, kvraw, kr, pos, gq, gk);
    v_transpose<<<dim3(16, 64, 8), 256>>>(kvraw, gvt);
    // attention
    flash_f16<<<dim3(S_LEN / 128, 16), 256, FA5_BYTES>>>(gq, gk, gvt, gattn);
    // output projection
    sgemm_db<128><<<dim3(8, 32), 256>>>(gattn, w_o_w, w_o_b, out,
                                        T_TOK, DIMM, 2048);
}

// round 9
// speedup vs baseline: 2.9913x; 1.3925x over previous
#include <cuda_runtime.h>
#include <cuda_fp16.h>
#include <math.h>
#include <stdint.h>

// ---------------- problem constants ----------------
#define T_TOK 4096
#define S_LEN 2048
#define DIMM 1024
#define QC 128
#define KVC 128
#define KROPE 64
#define VHD 256
#define HD 128

// ---------------- scratch ----------------
__device__ float g_dq[T_TOK * QC];
__device__ float g_dkv[T_TOK * (KVC + KROPE)];
__device__ float g_krope[T_TOK * KROPE];
__device__ float g_qraw[(size_t)T_TOK * 1024];
__device__ float g_kvraw[(size_t)T_TOK * 2560];
__device__ __half g_xh[(size_t)T_TOK * DIMM];
__device__ __half g_wdq[DIMM * QC];
__device__ __half g_wdkv[DIMM * 192];
__device__ __half g_wuq[QC * 1024];
__device__ __half g_wuk[KVC * 2560];
__device__ __half g_wo[(size_t)2048 * DIMM];
__device__ __half g_cqh[T_TOK * QC];
__device__ __half g_ckvh[T_TOK * KVC];
__device__ __half g_qh[(size_t)16 * S_LEN * HD];    // [bh][s][128]
__device__ __half g_kh[(size_t)16 * S_LEN * HD];    // [bh][s][128]
__device__ __half g_vth[(size_t)16 * VHD * S_LEN];  // [bh][n][s] (V^T)
__device__ __half g_attnh[(size_t)T_TOK * 2048];

// ---------------- helpers ----------------
__device__ __forceinline__ void mma_f16(float c[4], const uint32_t a[4], const uint32_t b[2]) {
    asm volatile(
        "mma.sync.aligned.m16n8k16.row.col.f32.f16.f16.f32 "
        "{%0,%1,%2,%3},{%4,%5,%6,%7},{%8,%9},{%0,%1,%2,%3};"
        : "+f"(c[0]), "+f"(c[1]), "+f"(c[2]), "+f"(c[3])
        : "r"(a[0]), "r"(a[1]), "r"(a[2]), "r"(a[3]), "r"(b[0]), "r"(b[1]));
}

__device__ __forceinline__ void ldsm4(uint32_t r[4], uint32_t saddr) {
    asm volatile("ldmatrix.sync.aligned.m8n8.x4.shared.b16 {%0,%1,%2,%3}, [%4];"
        : "=r"(r[0]), "=r"(r[1]), "=r"(r[2]), "=r"(r[3]) : "r"(saddr));
}
__device__ __forceinline__ void ldsm4t(uint32_t r[4], uint32_t saddr) {
    asm volatile("ldmatrix.sync.aligned.m8n8.x4.trans.shared.b16 {%0,%1,%2,%3}, [%4];"
        : "=r"(r[0]), "=r"(r[1]), "=r"(r[2]), "=r"(r[3]) : "r"(saddr));
}

__device__ __forceinline__ void cp_async16(void* smem_dst, const void* gsrc) {
    uint32_t s = (uint32_t)__cvta_generic_to_shared(smem_dst);
    asm volatile("cp.async.ca.shared.global [%0], [%1], 16;\n" :: "r"(s), "l"(gsrc));
}
#define CP_COMMIT() asm volatile("cp.async.commit_group;\n" ::: "memory")
#define CP_WAIT1()  asm volatile("cp.async.wait_group 1;\n" ::: "memory")
#define CP_WAIT0()  asm volatile("cp.async.wait_group 0;\n" ::: "memory")

__device__ __forceinline__ uint32_t packh2(float lo, float hi) {
    __half2 h = __floats2half2_rn(lo, hi);
    return *(uint32_t*)&h;
}

// ---------------- f32 -> f16 convert ----------------
__global__ __launch_bounds__(256) void f32_to_f16(
    const float* __restrict__ in, __half* __restrict__ out, int n)
{
    int i = (blockIdx.x * 256 + threadIdx.x) * 4;
    if (i < n) {
        float4 v = *(const float4*)&in[i];
        *(__half2*)&out[i]     = __floats2half2_rn(v.x, v.y);
        *(__half2*)&out[i + 2] = __floats2half2_rn(v.z, v.w);
    }
}

// ---------------- fp16 tensor-core GEMM ----------------
// C[M,N] = A[M,K] @ W[K,N] + bias. BM=128, BK=32, 256 threads, 8 warps (4x2).
// A fp16 [m][k], W fp16 [k][n]; ldmatrix A, ldmatrix.trans B; cp.async db-buffer.
template<int BN>
__global__ __launch_bounds__(256) void hgemm(
    const __half* __restrict__ A, const __half* __restrict__ W,
    const float* __restrict__ bias, float* __restrict__ C,
    int M, int N, int K)
{
    constexpr int BM = 128, BK = 32;
    constexpr int LDA = BK + 8;      // 40 halves (80B stride, conflict-free)
    constexpr int LDB = BN + 8;      // 136/72 halves
    constexpr int WN = BN / 2;       // warp n-width
    constexpr int NB = WN / 8;       // n8 blocks per warp
    constexpr int NB16 = WN / 16;    // n16 blocks per warp
    __shared__ __half As[2][BM][LDA];
    __shared__ __half Bs[2][BK][LDB];

    int tid = threadIdx.x, lane = tid & 31, w = tid >> 5;
    int g = lane >> 2, t = lane & 3;
    int wm = (w >> 1) * 32, wn = (w & 1) * WN;
    int m0 = blockIdx.y * BM, n0 = blockIdx.x * BN;

    // ldmatrix lane pattern: groups {r0-7,c0},{r8-15,c0},{r0-7,c8},{r8-15,c8}
    int rowX = (lane & 7) + ((lane >> 3) & 1) * 8;
    int colX = (lane >> 4) * 8;

    uint32_t aAddr = (uint32_t)__cvta_generic_to_shared(&As[0][wm + rowX][colX]);
    uint32_t bAddr = (uint32_t)__cvta_generic_to_shared(&Bs[0][rowX][wn + colX]);
    constexpr uint32_t ABUF = BM * LDA * 2;
    constexpr uint32_t BBUF = BK * LDB * 2;

    const __half* Ag = A + (size_t)m0 * K;
    const __half* Wg = W + n0;

    auto load = [&](int k0, int buf) {
        #pragma unroll
        for (int i = tid; i < BM * BK / 8; i += 256) {
            int r = i >> 2, c = (i & 3) * 8;
            cp_async16(&As[buf][r][c], &Ag[(size_t)r * K + k0 + c]);
        }
        #pragma unroll
        for (int i = tid; i < BK * BN / 8; i += 256) {
            int r = i / (BN / 8), c = (i % (BN / 8)) * 8;
            cp_async16(&Bs[buf][r][c], &Wg[(size_t)(k0 + r) * N + c]);
        }
    };

    float c[2][NB][4] = {};

    load(0, 0);
    CP_COMMIT();

    int nt = K / BK;
    for (int it = 0; it < nt; it++) {
        int buf = it & 1;
        CP_WAIT0();
        __syncthreads();
        if (it + 1 < nt) load((it + 1) * BK, buf ^ 1);
        CP_COMMIT();

        uint32_t af[2][2][4];
        #pragma unroll
        for (int i = 0; i < 2; i++)
            #pragma unroll
            for (int kg = 0; kg < 2; kg++)
                ldsm4(af[i][kg], aAddr + buf * ABUF + (i * 16 * LDA + kg * 16) * 2);

        #pragma unroll
        for (int kg = 0; kg < 2; kg++) {
            #pragma unroll
            for (int nb = 0; nb < NB16; nb++) {
                uint32_t bb[4];
                ldsm4t(bb, bAddr + buf * BBUF + (kg * 16 * LDB + nb * 16) * 2);
                #pragma unroll
                for (int i = 0; i < 2; i++) {
                    mma_f16(c[i][2 * nb],     af[i][kg], &bb[0]);
                    mma_f16(c[i][2 * nb + 1], af[i][kg], &bb[2]);
                }
            }
        }
    }

    #pragma unroll
    for (int i = 0; i < 2; i++) {
        #pragma unroll
        for (int nb = 0; nb < NB; nb++) {
            int row = m0 + wm + i * 16 + g;
            int col = n0 + wn + nb * 8 + 2 * t;
            float2 bb2 = *(const float2*)&bias[col];
            float2 o0 = { c[i][nb][0] + bb2.x, c[i][nb][1] + bb2.y };
            float2 o1 = { c[i][nb][2] + bb2.x, c[i][nb][3] + bb2.y };
            *(float2*)&C[(size_t)row * N + col] = o0;
            *(float2*)&C[(size_t)(row + 8) * N + col] = o1;
        }
    }
}

// ---------------- fused RMSNorm + K-rope (writes fp16 latents) ----------------
__global__ __launch_bounds__(128) void norm_rope_kernel(
    const float* __restrict__ dq, const float* __restrict__ dkv,
    const float* __restrict__ qnw, const float* __restrict__ kvnw,
    const int* __restrict__ pos_ids,
    __half* __restrict__ cq, __half* __restrict__ ckv, float* __restrict__ kr)
{
    int t = blockIdx.x, tid = threadIdx.x;
    int lane = tid & 31, wid = tid >> 5;
    __shared__ float r1[4], r2[4];
    float v1 = dq[t * 128 + tid];
    float v2 = dkv[t * 192 + tid];
    float s1 = v1 * v1, s2 = v2 * v2;
    #pragma unroll
    for (int o = 16; o; o >>= 1) {
        s1 += __shfl_xor_sync(0xffffffffu, s1, o);
        s2 += __shfl_xor_sync(0xffffffffu, s2, o);
    }
    if (!lane) { r1[wid] = s1; r2[wid] = s2; }
    __syncthreads();
    float t1 = r1[0] + r1[1] + r1[2] + r1[3];
    float t2 = r2[0] + r2[1] + r2[2] + r2[3];
    cq[t * 128 + tid]  = __float2half_rn(qnw[tid]  * v1 * rsqrtf(t1 * (1.0f / 128.0f) + 1e-8f));
    ckv[t * 128 + tid] = __float2half_rn(kvnw[tid] * v2 * rsqrtf(t2 * (1.0f / 128.0f) + 1e-8f));
    if (tid < 64) {
        int p = pos_ids[t];
        int i = tid >> 1;
        float invf = (float)exp(-(double)(2 * i) / 64.0 * log(10000.0));
        float ang = (float)p * invf;
        float sn, cs; sincosf(ang, &sn, &cs);
        float xe = dkv[t * 192 + 128 + 2 * i];
        float xo = dkv[t * 192 + 128 + 2 * i + 1];
        kr[t * 64 + tid] = (tid & 1) ? (xe * sn + xo * cs) : (xe * cs - xo * sn);
    }
}

// ---------------- scatter Q/K -> fp16 ----------------
__global__ __launch_bounds__(256) void scatter_qk(
    const float* __restrict__ qraw, const float* __restrict__ kvraw,
    const float* __restrict__ kr, const int* __restrict__ pos_ids,
    __half* __restrict__ gq, __half* __restrict__ gk)
{
    int t = blockIdx.x;
    int b = t >> 11, s = t & 2047;
    int tid = threadIdx.x;
    int p = pos_ids[t];
    const float* qrow = qraw + (size_t)t * 1024;
    const float* kvrow = kvraw + (size_t)t * 2560;
    for (int h = 0; h < 8; h++) {
        size_t qk_base = ((size_t)(b * 8 + h) * 2048 + s) * 128;
        if (tid < 128) {
            int d = tid;
            float val;
            if (d < 96) {
                val = qrow[h * 96 + d];
            } else {
                int j = d - 96, i = j >> 1;
                float invf = (float)exp(-(double)(2 * i) / 32.0 * log(10000.0));
                float ang = (float)p * invf;
                float sn, cs; sincosf(ang, &sn, &cs);
                const float* rb = qrow + 768 + h * 32;
                float xe = rb[2 * i], xo = rb[2 * i + 1];
                val = (j & 1) ? (xe * sn + xo * cs) : (xe * cs - xo * sn);
            }
            gq[qk_base + d] = __float2half_rn(val);
        } else {
            int d = tid - 128;
            float val = (d < 64) ? kvrow[h * 64 + d] : kr[t * 64 + (d - 64)];
            gk[qk_base + d] = __float2half_rn(val);
        }
    }
}

// ---------------- V transpose -> fp16 [bh][n][s] ----------------
__global__ __launch_bounds__(256) void v_transpose(
    const float* __restrict__ kvraw, __half* __restrict__ gvt)
{
    __shared__ float ts[32][33];
    int bh = blockIdx.x;
    int s0 = blockIdx.y * 32, n0 = blockIdx.z * 32;
    int b = bh >> 3, h = bh & 7;
    int c = threadIdx.x & 31, r0 = threadIdx.x >> 5;
    #pragma unroll
    for (int rr = r0; rr < 32; rr += 8)
        ts[rr][c] = kvraw[(size_t)(b * 2048 + s0 + rr) * 2560 + 512 + h * 256 + n0 + c];
    __syncthreads();
    #pragma unroll
    for (int rr = r0; rr < 32; rr += 8)
        gvt[(size_t)(bh * 256 + n0 + rr) * 2048 + s0 + c] = __float2half_rn(ts[c][rr]);
}

// ---------------- fp16 flash attention (round-8, epilogue -> fp16) ----------------
#define LQ 136
#define LK 136
#define LV 72
#define FQ_H (128 * LQ)
#define FK_H (64 * LK)
#define FV_H (256 * LV)
#define FA5_BYTES ((FQ_H + FK_H + FV_H) * 2 + 256)

__global__ __launch_bounds__(256, 1) void flash_f16(
    const __half* __restrict__ Q, const __half* __restrict__ K,
    const __half* __restrict__ VT, __half* __restrict__ O)
{
    extern __shared__ __align__(16) __half smh[];
    __half* Qs = smh;            // [128][136]
    __half* Ks = Qs + FQ_H;      // [64][136]
    __half* Vs = Ks + FK_H;      // [256][72]

    int bh = blockIdx.y, q0 = blockIdx.x * 128;
    const __half* Qg = Q + ((size_t)bh * 2048 + q0) * 128;
    const __half* Kg = K + (size_t)bh * 2048 * 128;
    const __half* Vg = VT + (size_t)bh * 256 * 2048;
    int tid = threadIdx.x, lane = tid & 31, w = tid >> 5;
    int g = lane >> 2, t = lane & 3;
    int wm = w * 16;

    int rowA = (lane & 7) + ((lane >> 3) & 1) * 8;
    int colA = (lane >> 4) * 8;
    int rowB = (lane & 7) + ((lane >> 4) & 1) * 8;
    int colB = ((lane >> 3) & 1) * 8;

    uint32_t qA = (uint32_t)__cvta_generic_to_shared(&Qs[(wm + rowA) * LQ + colA]);
    uint32_t kB = (uint32_t)__cvta_generic_to_shared(&Ks[rowB * LK + colB]);
    uint32_t vB = (uint32_t)__cvta_generic_to_shared(&Vs[rowB * LV + colB]);

    auto loadK = [&](int kc) {
        const __half* Kc = Kg + (size_t)kc * 64 * 128;
        #pragma unroll
        for (int i = tid; i < 1024; i += 256) {
            int r = i >> 4, c = i & 15;
            cp_async16(&Ks[r * LK + c * 8], &Kc[r * 128 + c * 8]);
        }
    };
    auto loadV = [&](int kc) {
        #pragma unroll
        for (int i = tid; i < 2048; i += 256) {
            int r = i >> 3, c = i & 7;
            cp_async16(&Vs[r * LV + c * 8], &Vg[(size_t)r * 2048 + kc * 64 + c * 8]);
        }
    };

    for (int i = tid; i < 2048; i += 256) {
        int r = i >> 4, c = i & 15;
        *(uint4*)&Qs[r * LQ + c * 8] = *(const uint4*)&Qg[r * 128 + c * 8];
    }
    loadK(0); CP_COMMIT();
    loadV(0); CP_COMMIT();
    __syncthreads();

    uint32_t qf[8][4];
    #pragma unroll
    for (int kg = 0; kg < 8; kg++) ldsm4(qf[kg], qA + kg * 32);

    float m0 = -1e30f, m1 = -1e30f, l0 = 0.f, l1 = 0.f;
    float oc[32][4] = {};
    const float scale = 0.08838834764831845f;  // 1/sqrt(128)

    for (int kc = 0; kc < 32; kc++) {
        CP_WAIT1();
        __syncthreads();

        float sc[8][4] = {};
        #pragma unroll
        for (int kg = 0; kg < 8; kg++) {
            #pragma unroll
            for (int ng = 0; ng < 4; ng++) {
                uint32_t bb[4];
                ldsm4(bb, kB + ng * 16 * LK * 2 + kg * 32);
                mma_f16(sc[2 * ng],     qf[kg], &bb[0]);
                mma_f16(sc[2 * ng + 1], qf[kg], &bb[2]);
            }
        }
        __syncthreads();

        float mc0 = -1e30f, mc1 = -1e30f;
        #pragma unroll
        for (int j = 0; j < 8; j++) {
            sc[j][0] *= scale; sc[j][1] *= scale;
            sc[j][2] *= scale; sc[j][3] *= scale;
            mc0 = fmaxf(mc0, fmaxf(sc[j][0], sc[j][1]));
            mc1 = fmaxf(mc1, fmaxf(sc[j][2], sc[j][3]));
        }
        mc0 = fmaxf(mc0, __shfl_xor_sync(0xffffffffu, mc0, 1));
        mc0 = fmaxf(mc0, __shfl_xor_sync(0xffffffffu, mc0, 2));
        mc1 = fmaxf(mc1, __shfl_xor_sync(0xffffffffu, mc1, 1));
        mc1 = fmaxf(mc1, __shfl_xor_sync(0xffffffffu, mc1, 2));
        float mn0 = fmaxf(m0, mc0), mn1 = fmaxf(m1, mc1);
        float al0 = __expf(m0 - mn0), al1 = __expf(m1 - mn1);
        m0 = mn0; m1 = mn1;

        uint32_t ph[4][4];
        float ls0 = 0.f, ls1 = 0.f;
        #pragma unroll
        for (int j = 0; j < 8; j++) {
            float e0 = __expf(sc[j][0] - mn0);
            float e1 = __expf(sc[j][1] - mn0);
            float e2 = __expf(sc[j][2] - mn1);
            float e3 = __expf(sc[j][3] - mn1);
            ls0 += e0 + e1; ls1 += e2 + e3;
            int kg = j >> 1, hi = (j & 1) * 2;
            ph[kg][hi]     = packh2(e0, e1);
            ph[kg][hi + 1] = packh2(e2, e3);
        }
        ls0 += __shfl_xor_sync(0xffffffffu, ls0, 1);
        ls0 += __shfl_xor_sync(0xffffffffu, ls0, 2);
        ls1 += __shfl_xor_sync(0xffffffffu, ls1, 1);
        ls1 += __shfl_xor_sync(0xffffffffu, ls1, 2);
        l0 = l0 * al0 + ls0;
        l1 = l1 * al1 + ls1;

        if (kc + 1 < 32) loadK(kc + 1);
        CP_COMMIT();
        CP_WAIT1();
        __syncthreads();

        #pragma unroll
        for (int nt = 0; nt < 32; nt++) {
            oc[nt][0] *= al0; oc[nt][1] *= al0;
            oc[nt][2] *= al1; oc[nt][3] *= al1;
        }
        #pragma unroll
        for (int kg = 0; kg < 4; kg++) {
            #pragma unroll
            for (int ng = 0; ng < 16; ng++) {
                uint32_t bb[4];
                ldsm4(bb, vB + ng * 16 * LV * 2 + kg * 32);
                mma_f16(oc[2 * ng],     ph[kg], &bb[0]);
                mma_f16(oc[2 * ng + 1], ph[kg], &bb[2]);
            }
        }
        __syncthreads();
        if (kc + 1 < 32) loadV(kc + 1);
        CP_COMMIT();
    }

    // epilogue -> fp16 attn
    int b = bh >> 3, h = bh & 7;
    float inv0 = 1.0f / l0, inv1 = 1.0f / l1;
    int row0 = q0 + wm + g, row1 = row0 + 8;
    #pragma unroll
    for (int nt = 0; nt < 32; nt++) {
        int col = h * 256 + nt * 8 + 2 * t;
        uint32_t p0 = packh2(oc[nt][0] * inv0, oc[nt][1] * inv0);
        uint32_t p1 = packh2(oc[nt][2] * inv1, oc[nt][3] * inv1);
        *(uint32_t*)&O[((size_t)(b * 2048 + row0)) * 2048 + col] = p0;
        *(uint32_t*)&O[((size_t)(b * 2048 + row1)) * 2048 + col] = p1;
    }
}

// ---------------- launch ----------------
extern "C" void kernel_launch(void* const* d_in, const int* in_sizes, int n_in,
                              void* d_out, int out_size)
{
    const float* x         = (const float*)d_in[0];
    const int*   pos       = (const int*)d_in[1];
    const float* w_dq_w    = (const float*)d_in[2];
    const float* w_dq_b    = (const float*)d_in[3];
    const float* q_norm_w  = (const float*)d_in[4];
    const float* w_uq_qr_w = (const float*)d_in[5];
    const float* w_uq_qr_b = (const float*)d_in[6];
    const float* w_dkv_w   = (const float*)d_in[7];
    const float* w_dkv_b   = (const float*)d_in[8];
    const float* kv_norm_w = (const float*)d_in[9];
    const float* w_uk_w    = (const float*)d_in[10];
    const float* w_uk_b    = (const float*)d_in[11];
    const float* w_o_w     = (const float*)d_in[12];
    const float* w_o_b     = (const float*)d_in[13];
    float* out = (float*)d_out;

    float *dq, *dkv, *kr, *qraw, *kvraw;
    __half *xh, *wdq, *wdkv, *wuq, *wuk, *wo, *cqh, *ckvh, *gq, *gk, *gvt, *attnh;
    cudaGetSymbolAddress((void**)&dq, g_dq);
    cudaGetSymbolAddress((void**)&dkv, g_dkv);
    cudaGetSymbolAddress((void**)&kr, g_krope);
    cudaGetSymbolAddress((void**)&qraw, g_qraw);
    cudaGetSymbolAddress((void**)&kvraw, g_kvraw);
    cudaGetSymbolAddress((void**)&xh, g_xh);
    cudaGetSymbolAddress((void**)&wdq, g_wdq);
    cudaGetSymbolAddress((void**)&wdkv, g_wdkv);
    cudaGetSymbolAddress((void**)&wuq, g_wuq);
    cudaGetSymbolAddress((void**)&wuk, g_wuk);
    cudaGetSymbolAddress((void**)&wo, g_wo);
    cudaGetSymbolAddress((void**)&cqh, g_cqh);
    cudaGetSymbolAddress((void**)&ckvh, g_ckvh);
    cudaGetSymbolAddress((void**)&gq, g_qh);
    cudaGetSymbolAddress((void**)&gk, g_kh);
    cudaGetSymbolAddress((void**)&gvt, g_vth);
    cudaGetSymbolAddress((void**)&attnh, g_attnh);

    cudaFuncSetAttribute(flash_f16, cudaFuncAttributeMaxDynamicSharedMemorySize,
                         FA5_BYTES);

    // fp16 conversions (x + all weights)
    f32_to_f16<<<4096, 256>>>(x, xh, T_TOK * DIMM);
    f32_to_f16<<<128, 256>>>(w_dq_w, wdq, DIMM * QC);
    f32_to_f16<<<192, 256>>>(w_dkv_w, wdkv, DIMM * 192);
    f32_to_f16<<<128, 256>>>(w_uq_qr_w, wuq, QC * 1024);
    f32_to_f16<<<320, 256>>>(w_uk_w, wuk, KVC * 2560);
    f32_to_f16<<<2048, 256>>>(w_o_w, wo, 2048 * DIMM);

    // down projections
    hgemm<64><<<dim3(2, 32), 256>>>(xh, wdq, w_dq_b, dq, T_TOK, QC, DIMM);
    hgemm<64><<<dim3(3, 32), 256>>>(xh, wdkv, w_dkv_b, dkv, T_TOK, 192, DIMM);
    // rmsnorm + k rope (fp16 latents out)
    norm_rope_kernel<<<T_TOK, 128>>>(dq, dkv, q_norm_w, kv_norm_w, pos, cqh, ckvh, kr);
    // up projections
    hgemm<128><<<dim3(8, 32), 256>>>(cqh, wuq, w_uq_qr_b, qraw, T_TOK, 1024, QC);
    hgemm<128><<<dim3(20, 32), 256>>>(ckvh, wuk, w_uk_b, kvraw, T_TOK, 2560, KVC);
    // build per-head states (fp16)
    scatter_qk<<<T_TOK, 256>>>(qraw, kvraw, kr, pos, gq, gk);
    v_transpose<<<dim3(16, 64, 8), 256>>>(kvraw, gvt);
    // attention (fp16 attn out)
    flash_f16<<<dim3(S_LEN / 128, 16), 256, FA5_BYTES>>>(gq, gk, gvt, attnh);
    // output projection
    hgemm<128><<<dim3(8, 32), 256>>>(attnh, wo, w_o_b, out, T_TOK, DIMM, 2048);
}

// round 10
// speedup vs baseline: 3.3117x; 1.1071x over previous
#include <cuda_runtime.h>
#include <cuda_fp16.h>
#include <math.h>
#include <stdint.h>

// ---------------- problem constants ----------------
#define T_TOK 4096
#define S_LEN 2048
#define DIMM 1024
#define QC 128
#define KVC 128
#define KROPE 64
#define VHD 256
#define HD 128

// ---------------- scratch ----------------
__device__ float g_dq[T_TOK * QC];
__device__ float g_dkv[T_TOK * (KVC + KROPE)];
__device__ float g_krope[T_TOK * KROPE];
__device__ __half g_qrawh[(size_t)T_TOK * 1024];
__device__ __half g_kvrawh[(size_t)T_TOK * 2560];
__device__ __half g_xh[(size_t)T_TOK * DIMM];
__device__ __half g_wdq[DIMM * QC];
__device__ __half g_wdkv[DIMM * 192];
__device__ __half g_wuq[QC * 1024];
__device__ __half g_wuk[KVC * 2560];
__device__ __half g_wo[(size_t)2048 * DIMM];
__device__ __half g_cqh[T_TOK * QC];
__device__ __half g_ckvh[T_TOK * KVC];
__device__ __half g_qh[(size_t)16 * S_LEN * HD];    // [bh][s][128]
__device__ __half g_kh[(size_t)16 * S_LEN * HD];    // [bh][s][128]
__device__ __half g_vth[(size_t)16 * VHD * S_LEN];  // [bh][n][s] (V^T)
__device__ __half g_attnh[(size_t)T_TOK * 2048];

// ---------------- helpers ----------------
__device__ __forceinline__ void mma_f16(float c[4], const uint32_t a[4], const uint32_t b[2]) {
    asm volatile(
        "mma.sync.aligned.m16n8k16.row.col.f32.f16.f16.f32 "
        "{%0,%1,%2,%3},{%4,%5,%6,%7},{%8,%9},{%0,%1,%2,%3};"
        : "+f"(c[0]), "+f"(c[1]), "+f"(c[2]), "+f"(c[3])
        : "r"(a[0]), "r"(a[1]), "r"(a[2]), "r"(a[3]), "r"(b[0]), "r"(b[1]));
}

__device__ __forceinline__ void ldsm4(uint32_t r[4], uint32_t saddr) {
    asm volatile("ldmatrix.sync.aligned.m8n8.x4.shared.b16 {%0,%1,%2,%3}, [%4];"
        : "=r"(r[0]), "=r"(r[1]), "=r"(r[2]), "=r"(r[3]) : "r"(saddr));
}
__device__ __forceinline__ void ldsm4t(uint32_t r[4], uint32_t saddr) {
    asm volatile("ldmatrix.sync.aligned.m8n8.x4.trans.shared.b16 {%0,%1,%2,%3}, [%4];"
        : "=r"(r[0]), "=r"(r[1]), "=r"(r[2]), "=r"(r[3]) : "r"(saddr));
}

__device__ __forceinline__ void cp_async16(void* smem_dst, const void* gsrc) {
    uint32_t s = (uint32_t)__cvta_generic_to_shared(smem_dst);
    asm volatile("cp.async.ca.shared.global [%0], [%1], 16;\n" :: "r"(s), "l"(gsrc));
}
#define CP_COMMIT() asm volatile("cp.async.commit_group;\n" ::: "memory")
#define CP_WAIT1()  asm volatile("cp.async.wait_group 1;\n" ::: "memory")

__device__ __forceinline__ uint32_t packh2(float lo, float hi) {
    __half2 h = __floats2half2_rn(lo, hi);
    return *(uint32_t*)&h;
}

// ---------------- fused f32 -> f16 conversion of x + all weights ----------------
#define CV_X   (T_TOK * DIMM)            // 4194304
#define CV_DQ  (DIMM * QC)               // 131072
#define CV_DKV (DIMM * 192)              // 196608
#define CV_UQ  (QC * 1024)               // 131072
#define CV_UK  (KVC * 2560)              // 327680
#define CV_WO  (2048 * DIMM)             // 2097152
#define CV_TOTAL (CV_X + CV_DQ + CV_DKV + CV_UQ + CV_UK + CV_WO)
#define CV_QUADS (CV_TOTAL / 4)          // 1769472

__global__ __launch_bounds__(256) void convert_all(
    const float* __restrict__ x,   const float* __restrict__ wdq,
    const float* __restrict__ wdkv,const float* __restrict__ wuq,
    const float* __restrict__ wuk, const float* __restrict__ wo,
    __half* __restrict__ xh,   __half* __restrict__ wdqh,
    __half* __restrict__ wdkvh,__half* __restrict__ wuqh,
    __half* __restrict__ wukh, __half* __restrict__ woh)
{
    long long i = ((long long)blockIdx.x * 256 + threadIdx.x) * 4;
    if (i >= CV_TOTAL) return;
    const float* src;
    __half* dst;
    long long off = i;
    if (off < CV_X)                    { src = x;    dst = xh; }
    else if ((off -= CV_X)   < CV_DQ)  { src = wdq;  dst = wdqh; }
    else if ((off -= CV_DQ)  < CV_DKV) { src = wdkv; dst = wdkvh; }
    else if ((off -= CV_DKV) < CV_UQ)  { src = wuq;  dst = wuqh; }
    else if ((off -= CV_UQ)  < CV_UK)  { src = wuk;  dst = wukh; }
    else { off -= CV_UK;                 src = wo;   dst = woh; }
    float4 v = *(const float4*)&src[off];
    *(__half2*)&dst[off]     = __floats2half2_rn(v.x, v.y);
    *(__half2*)&dst[off + 2] = __floats2half2_rn(v.z, v.w);
}

// ---------------- fp16 tensor-core GEMM, 3-stage cp.async pipeline ----------------
// C[M,N] = A[M,K] @ W[K,N] + bias. BM=128, BK=32, 256 threads, 8 warps (4x2).
// HALF_OUT selects fp16 vs fp32 output.
template<int BN, bool HALF_OUT>
__global__ __launch_bounds__(256, 2) void hgemm(
    const __half* __restrict__ A, const __half* __restrict__ W,
    const float* __restrict__ bias, void* __restrict__ Cv,
    int M, int N, int K)
{
    constexpr int BM = 128, BK = 32, ST = 3;
    constexpr int LDA = BK + 8;
    constexpr int LDB = BN + 8;
    constexpr int WN = BN / 2;
    constexpr int NB = WN / 8;
    constexpr int NB16 = WN / 16;
    __shared__ __half As[ST][BM][LDA];
    __shared__ __half Bs[ST][BK][LDB];

    int tid = threadIdx.x, lane = tid & 31, w = tid >> 5;
    int g = lane >> 2, t = lane & 3;
    int wm = (w >> 1) * 32, wn = (w & 1) * WN;
    int m0 = blockIdx.y * BM, n0 = blockIdx.x * BN;

    int rowX = (lane & 7) + ((lane >> 3) & 1) * 8;
    int colX = (lane >> 4) * 8;

    uint32_t aAddr = (uint32_t)__cvta_generic_to_shared(&As[0][wm + rowX][colX]);
    uint32_t bAddr = (uint32_t)__cvta_generic_to_shared(&Bs[0][rowX][wn + colX]);
    constexpr uint32_t ABUF = BM * LDA * 2;
    constexpr uint32_t BBUF = BK * LDB * 2;

    const __half* Ag = A + (size_t)m0 * K;
    const __half* Wg = W + n0;

    auto load = [&](int k0, int buf) {
        #pragma unroll
        for (int i = tid; i < BM * BK / 8; i += 256) {
            int r = i >> 2, c = (i & 3) * 8;
            cp_async16(&As[buf][r][c], &Ag[(size_t)r * K + k0 + c]);
        }
        #pragma unroll
        for (int i = tid; i < BK * BN / 8; i += 256) {
            int r = i / (BN / 8), c = (i % (BN / 8)) * 8;
            cp_async16(&Bs[buf][r][c], &Wg[(size_t)(k0 + r) * N + c]);
        }
    };

    float c[2][NB][4] = {};

    int nt = K / BK;
    load(0, 0); CP_COMMIT();
    load(BK, 1); CP_COMMIT();

    for (int it = 0; it < nt; it++) {
        int buf = it % 3;
        CP_WAIT1();                       // group(it) complete
        __syncthreads();
        if (it + 2 < nt) load((it + 2) * BK, (it + 2) % 3);
        CP_COMMIT();

        uint32_t af[2][2][4];
        #pragma unroll
        for (int i = 0; i < 2; i++)
            #pragma unroll
            for (int kg = 0; kg < 2; kg++)
                ldsm4(af[i][kg], aAddr + buf * ABUF + (i * 16 * LDA + kg * 16) * 2);

        #pragma unroll
        for (int kg = 0; kg < 2; kg++) {
            #pragma unroll
            for (int nb = 0; nb < NB16; nb++) {
                uint32_t bb[4];
                ldsm4t(bb, bAddr + buf * BBUF + (kg * 16 * LDB + nb * 16) * 2);
                #pragma unroll
                for (int i = 0; i < 2; i++) {
                    mma_f16(c[i][2 * nb],     af[i][kg], &bb[0]);
                    mma_f16(c[i][2 * nb + 1], af[i][kg], &bb[2]);
                }
            }
        }
    }

    #pragma unroll
    for (int i = 0; i < 2; i++) {
        #pragma unroll
        for (int nb = 0; nb < NB; nb++) {
            int row = m0 + wm + i * 16 + g;
            int col = n0 + wn + nb * 8 + 2 * t;
            float2 bb2 = *(const float2*)&bias[col];
            float o00 = c[i][nb][0] + bb2.x, o01 = c[i][nb][1] + bb2.y;
            float o10 = c[i][nb][2] + bb2.x, o11 = c[i][nb][3] + bb2.y;
            if (HALF_OUT) {
                __half* C = (__half*)Cv;
                *(uint32_t*)&C[(size_t)row * N + col] = packh2(o00, o01);
                *(uint32_t*)&C[(size_t)(row + 8) * N + col] = packh2(o10, o11);
            } else {
                float* C = (float*)Cv;
                float2 v0 = { o00, o01 }, v1 = { o10, o11 };
                *(float2*)&C[(size_t)row * N + col] = v0;
                *(float2*)&C[(size_t)(row + 8) * N + col] = v1;
            }
        }
    }
}

// ---------------- fused RMSNorm + K-rope (writes fp16 latents) ----------------
__global__ __launch_bounds__(128) void norm_rope_kernel(
    const float* __restrict__ dq, const float* __restrict__ dkv,
    const float* __restrict__ qnw, const float* __restrict__ kvnw,
    const int* __restrict__ pos_ids,
    __half* __restrict__ cq, __half* __restrict__ ckv, float* __restrict__ kr)
{
    int t = blockIdx.x, tid = threadIdx.x;
    int lane = tid & 31, wid = tid >> 5;
    __shared__ float r1[4], r2[4];
    float v1 = dq[t * 128 + tid];
    float v2 = dkv[t * 192 + tid];
    float s1 = v1 * v1, s2 = v2 * v2;
    #pragma unroll
    for (int o = 16; o; o >>= 1) {
        s1 += __shfl_xor_sync(0xffffffffu, s1, o);
        s2 += __shfl_xor_sync(0xffffffffu, s2, o);
    }
    if (!lane) { r1[wid] = s1; r2[wid] = s2; }
    __syncthreads();
    float t1 = r1[0] + r1[1] + r1[2] + r1[3];
    float t2 = r2[0] + r2[1] + r2[2] + r2[3];
    cq[t * 128 + tid]  = __float2half_rn(qnw[tid]  * v1 * rsqrtf(t1 * (1.0f / 128.0f) + 1e-8f));
    ckv[t * 128 + tid] = __float2half_rn(kvnw[tid] * v2 * rsqrtf(t2 * (1.0f / 128.0f) + 1e-8f));
    if (tid < 64) {
        int p = pos_ids[t];
        int i = tid >> 1;
        float invf = (float)exp(-(double)(2 * i) / 64.0 * log(10000.0));
        float ang = (float)p * invf;
        float sn, cs; sincosf(ang, &sn, &cs);
        float xe = dkv[t * 192 + 128 + 2 * i];
        float xo = dkv[t * 192 + 128 + 2 * i + 1];
        kr[t * 64 + tid] = (tid & 1) ? (xe * sn + xo * cs) : (xe * cs - xo * sn);
    }
}

// ---------------- scatter Q/K (fp16 in, fp16 out) ----------------
__global__ __launch_bounds__(256) void scatter_qk(
    const __half* __restrict__ qraw, const __half* __restrict__ kvraw,
    const float* __restrict__ kr, const int* __restrict__ pos_ids,
    __half* __restrict__ gq, __half* __restrict__ gk)
{
    int t = blockIdx.x;
    int b = t >> 11, s = t & 2047;
    int tid = threadIdx.x;
    int p = pos_ids[t];
    const __half* qrow = qraw + (size_t)t * 1024;
    const __half* kvrow = kvraw + (size_t)t * 2560;
    for (int h = 0; h < 8; h++) {
        size_t qk_base = ((size_t)(b * 8 + h) * 2048 + s) * 128;
        if (tid < 128) {
            int d = tid;
            __half val;
            if (d < 96) {
                val = qrow[h * 96 + d];
            } else {
                int j = d - 96, i = j >> 1;
                float invf = (float)exp(-(double)(2 * i) / 32.0 * log(10000.0));
                float ang = (float)p * invf;
                float sn, cs; sincosf(ang, &sn, &cs);
                const __half* rb = qrow + 768 + h * 32;
                float xe = __half2float(rb[2 * i]), xo = __half2float(rb[2 * i + 1]);
                val = __float2half_rn((j & 1) ? (xe * sn + xo * cs) : (xe * cs - xo * sn));
            }
            gq[qk_base + d] = val;
        } else {
            int d = tid - 128;
            gk[qk_base + d] = (d < 64) ? kvrow[h * 64 + d]
                                       : __float2half_rn(kr[t * 64 + (d - 64)]);
        }
    }
}

// ---------------- V transpose (fp16 in) -> fp16 [bh][n][s] ----------------
__global__ __launch_bounds__(256) void v_transpose(
    const __half* __restrict__ kvraw, __half* __restrict__ gvt)
{
    __shared__ __half ts[32][36];
    int bh = blockIdx.x;
    int s0 = blockIdx.y * 32, n0 = blockIdx.z * 32;
    int b = bh >> 3, h = bh & 7;
    int c = threadIdx.x & 31, r0 = threadIdx.x >> 5;
    #pragma unroll
    for (int rr = r0; rr < 32; rr += 8)
        ts[rr][c] = kvraw[(size_t)(b * 2048 + s0 + rr) * 2560 + 512 + h * 256 + n0 + c];
    __syncthreads();
    #pragma unroll
    for (int rr = r0; rr < 32; rr += 8)
        gvt[(size_t)(bh * 256 + n0 + rr) * 2048 + s0 + c] = ts[c][rr];
}

// ---------------- fp16 flash attention (round-9, unchanged) ----------------
#define LQ 136
#define LK 136
#define LV 72
#define FQ_H (128 * LQ)
#define FK_H (64 * LK)
#define FV_H (256 * LV)
#define FA5_BYTES ((FQ_H + FK_H + FV_H) * 2 + 256)

__global__ __launch_bounds__(256, 1) void flash_f16(
    const __half* __restrict__ Q, const __half* __restrict__ K,
    const __half* __restrict__ VT, __half* __restrict__ O)
{
    extern __shared__ __align__(16) __half smh[];
    __half* Qs = smh;            // [128][136]
    __half* Ks = Qs + FQ_H;      // [64][136]
    __half* Vs = Ks + FK_H;      // [256][72]

    int bh = blockIdx.y, q0 = blockIdx.x * 128;
    const __half* Qg = Q + ((size_t)bh * 2048 + q0) * 128;
    const __half* Kg = K + (size_t)bh * 2048 * 128;
    const __half* Vg = VT + (size_t)bh * 256 * 2048;
    int tid = threadIdx.x, lane = tid & 31, w = tid >> 5;
    int g = lane >> 2, t = lane & 3;
    int wm = w * 16;

    int rowA = (lane & 7) + ((lane >> 3) & 1) * 8;
    int colA = (lane >> 4) * 8;
    int rowB = (lane & 7) + ((lane >> 4) & 1) * 8;
    int colB = ((lane >> 3) & 1) * 8;

    uint32_t qA = (uint32_t)__cvta_generic_to_shared(&Qs[(wm + rowA) * LQ + colA]);
    uint32_t kB = (uint32_t)__cvta_generic_to_shared(&Ks[rowB * LK + colB]);
    uint32_t vB = (uint32_t)__cvta_generic_to_shared(&Vs[rowB * LV + colB]);

    auto loadK = [&](int kc) {
        const __half* Kc = Kg + (size_t)kc * 64 * 128;
        #pragma unroll
        for (int i = tid; i < 1024; i += 256) {
            int r = i >> 4, c = i & 15;
            cp_async16(&Ks[r * LK + c * 8], &Kc[r * 128 + c * 8]);
        }
    };
    auto loadV = [&](int kc) {
        #pragma unroll
        for (int i = tid; i < 2048; i += 256) {
            int r = i >> 3, c = i & 7;
            cp_async16(&Vs[r * LV + c * 8], &Vg[(size_t)r * 2048 + kc * 64 + c * 8]);
        }
    };

    for (int i = tid; i < 2048; i += 256) {
        int r = i >> 4, c = i & 15;
        *(uint4*)&Qs[r * LQ + c * 8] = *(const uint4*)&Qg[r * 128 + c * 8];
    }
    loadK(0); CP_COMMIT();
    loadV(0); CP_COMMIT();
    __syncthreads();

    uint32_t qf[8][4];
    #pragma unroll
    for (int kg = 0; kg < 8; kg++) ldsm4(qf[kg], qA + kg * 32);

    float m0 = -1e30f, m1 = -1e30f, l0 = 0.f, l1 = 0.f;
    float oc[32][4] = {};
    const float scale = 0.08838834764831845f;  // 1/sqrt(128)

    for (int kc = 0; kc < 32; kc++) {
        CP_WAIT1();
        __syncthreads();

        float sc[8][4] = {};
        #pragma unroll
        for (int kg = 0; kg < 8; kg++) {
            #pragma unroll
            for (int ng = 0; ng < 4; ng++) {
                uint32_t bb[4];
                ldsm4(bb, kB + ng * 16 * LK * 2 + kg * 32);
                mma_f16(sc[2 * ng],     qf[kg], &bb[0]);
                mma_f16(sc[2 * ng + 1], qf[kg], &bb[2]);
            }
        }
        __syncthreads();

        float mc0 = -1e30f, mc1 = -1e30f;
        #pragma unroll
        for (int j = 0; j < 8; j++) {
            sc[j][0] *= scale; sc[j][1] *= scale;
            sc[j][2] *= scale; sc[j][3] *= scale;
            mc0 = fmaxf(mc0, fmaxf(sc[j][0], sc[j][1]));
            mc1 = fmaxf(mc1, fmaxf(sc[j][2], sc[j][3]));
        }
        mc0 = fmaxf(mc0, __shfl_xor_sync(0xffffffffu, mc0, 1));
        mc0 = fmaxf(mc0, __shfl_xor_sync(0xffffffffu, mc0, 2));
        mc1 = fmaxf(mc1, __shfl_xor_sync(0xffffffffu, mc1, 1));
        mc1 = fmaxf(mc1, __shfl_xor_sync(0xffffffffu, mc1, 2));
        float mn0 = fmaxf(m0, mc0), mn1 = fmaxf(m1, mc1);
        float al0 = __expf(m0 - mn0), al1 = __expf(m1 - mn1);
        m0 = mn0; m1 = mn1;

        uint32_t ph[4][4];
        float ls0 = 0.f, ls1 = 0.f;
        #pragma unroll
        for (int j = 0; j < 8; j++) {
            float e0 = __expf(sc[j][0] - mn0);
            float e1 = __expf(sc[j][1] - mn0);
            float e2 = __expf(sc[j][2] - mn1);
            float e3 = __expf(sc[j][3] - mn1);
            ls0 += e0 + e1; ls1 += e2 + e3;
            int kg = j >> 1, hi = (j & 1) * 2;
            ph[kg][hi]     = packh2(e0, e1);
            ph[kg][hi + 1] = packh2(e2, e3);
        }
        ls0 += __shfl_xor_sync(0xffffffffu, ls0, 1);
        ls0 += __shfl_xor_sync(0xffffffffu, ls0, 2);
        ls1 += __shfl_xor_sync(0xffffffffu, ls1, 1);
        ls1 += __shfl_xor_sync(0xffffffffu, ls1, 2);
        l0 = l0 * al0 + ls0;
        l1 = l1 * al1 + ls1;

        if (kc + 1 < 32) loadK(kc + 1);
        CP_COMMIT();
        CP_WAIT1();
        __syncthreads();

        #pragma unroll
        for (int nt = 0; nt < 32; nt++) {
            oc[nt][0] *= al0; oc[nt][1] *= al0;
            oc[nt][2] *= al1; oc[nt][3] *= al1;
        }
        #pragma unroll
        for (int kg = 0; kg < 4; kg++) {
            #pragma unroll
            for (int ng = 0; ng < 16; ng++) {
                uint32_t bb[4];
                ldsm4(bb, vB + ng * 16 * LV * 2 + kg * 32);
                mma_f16(oc[2 * ng],     ph[kg], &bb[0]);
                mma_f16(oc[2 * ng + 1], ph[kg], &bb[2]);
            }
        }
        __syncthreads();
        if (kc + 1 < 32) loadV(kc + 1);
        CP_COMMIT();
    }

    int b = bh >> 3, h = bh & 7;
    float inv0 = 1.0f / l0, inv1 = 1.0f / l1;
    int row0 = q0 + wm + g, row1 = row0 + 8;
    #pragma unroll
    for (int nt = 0; nt < 32; nt++) {
        int col = h * 256 + nt * 8 + 2 * t;
        uint32_t p0 = packh2(oc[nt][0] * inv0, oc[nt][1] * inv0);
        uint32_t p1 = packh2(oc[nt][2] * inv1, oc[nt][3] * inv1);
        *(uint32_t*)&O[((size_t)(b * 2048 + row0)) * 2048 + col] = p0;
        *(uint32_t*)&O[((size_t)(b * 2048 + row1)) * 2048 + col] = p1;
    }
}

// ---------------- launch ----------------
extern "C" void kernel_launch(void* const* d_in, const int* in_sizes, int n_in,
                              void* d_out, int out_size)
{
    const float* x         = (const float*)d_in[0];
    const int*   pos       = (const int*)d_in[1];
    const float* w_dq_w    = (const float*)d_in[2];
    const float* w_dq_b    = (const float*)d_in[3];
    const float* q_norm_w  = (const float*)d_in[4];
    const float* w_uq_qr_w = (const float*)d_in[5];
    const float* w_uq_qr_b = (const float*)d_in[6];
    const float* w_dkv_w   = (const float*)d_in[7];
    const float* w_dkv_b   = (const float*)d_in[8];
    const float* kv_norm_w = (const float*)d_in[9];
    const float* w_uk_w    = (const float*)d_in[10];
    const float* w_uk_b    = (const float*)d_in[11];
    const float* w_o_w     = (const float*)d_in[12];
    const float* w_o_b     = (const float*)d_in[13];
    float* out = (float*)d_out;

    float *dq, *dkv, *kr;
    __half *xh, *wdq, *wdkv, *wuq, *wuk, *wo, *cqh, *ckvh;
    __half *qrawh, *kvrawh, *gq, *gk, *gvt, *attnh;
    cudaGetSymbolAddress((void**)&dq, g_dq);
    cudaGetSymbolAddress((void**)&dkv, g_dkv);
    cudaGetSymbolAddress((void**)&kr, g_krope);
    cudaGetSymbolAddress((void**)&qrawh, g_qrawh);
    cudaGetSymbolAddress((void**)&kvrawh, g_kvrawh);
    cudaGetSymbolAddress((void**)&xh, g_xh);
    cudaGetSymbolAddress((void**)&wdq, g_wdq);
    cudaGetSymbolAddress((void**)&wdkv, g_wdkv);
    cudaGetSymbolAddress((void**)&wuq, g_wuq);
    cudaGetSymbolAddress((void**)&wuk, g_wuk);
    cudaGetSymbolAddress((void**)&wo, g_wo);
    cudaGetSymbolAddress((void**)&cqh, g_cqh);
    cudaGetSymbolAddress((void**)&ckvh, g_ckvh);
    cudaGetSymbolAddress((void**)&gq, g_qh);
    cudaGetSymbolAddress((void**)&gk, g_kh);
    cudaGetSymbolAddress((void**)&gvt, g_vth);
    cudaGetSymbolAddress((void**)&attnh, g_attnh);

    cudaFuncSetAttribute(flash_f16, cudaFuncAttributeMaxDynamicSharedMemorySize,
                         FA5_BYTES);

    // one fused fp16 conversion pass
    convert_all<<<(CV_QUADS + 255) / 256, 256>>>(
        x, w_dq_w, w_dkv_w, w_uq_qr_w, w_uk_w, w_o_w,
        xh, wdq, wdkv, wuq, wuk, wo);

    // down projections (fp32 out for norm)
    hgemm<64, false><<<dim3(2, 32), 256>>>(xh, wdq, w_dq_b, dq, T_TOK, QC, DIMM);
    hgemm<64, false><<<dim3(3, 32), 256>>>(xh, wdkv, w_dkv_b, dkv, T_TOK, 192, DIMM);
    // rmsnorm + k rope (fp16 latents)
    norm_rope_kernel<<<T_TOK, 128>>>(dq, dkv, q_norm_w, kv_norm_w, pos, cqh, ckvh, kr);
    // up projections (fp16 out)
    hgemm<128, true><<<dim3(8, 32), 256>>>(cqh, wuq, w_uq_qr_b, qrawh, T_TOK, 1024, QC);
    hgemm<128, true><<<dim3(20, 32), 256>>>(ckvh, wuk, w_uk_b, kvrawh, T_TOK, 2560, KVC);
    // build per-head states
    scatter_qk<<<T_TOK, 256>>>(qrawh, kvrawh, kr, pos, gq, gk);
    v_transpose<<<dim3(16, 64, 8), 256>>>(kvrawh, gvt);
    // attention
    flash_f16<<<dim3(S_LEN / 128, 16), 256, FA5_BYTES>>>(gq, gk, gvt, attnh);
    // output projection (fp32 out)
    hgemm<128, false><<<dim3(8, 32), 256>>>(attnh, wo, w_o_b, out, T_TOK, DIMM, 2048);
}

// round 11
// speedup vs baseline: 4.6015x; 1.3895x over previous
#include <cuda_runtime.h>
#include <cuda_fp16.h>
#include <math.h>
#include <stdint.h>

// ---------------- problem constants ----------------
#define T_TOK 4096
#define S_LEN 2048
#define DIMM 1024
#define QC 128
#define KVC 128
#define KROPE 64
#define VHD 256
#define HD 128

// log2(10000) = 13.287712379549449
#define QR_EXP 0.8304820237218406f   // /16  (q rope, head_dim 32)
#define KR_EXP 0.4152410118609203f   // /32  (k rope, head_dim 64)

// ---------------- scratch ----------------
__device__ float  g_dqkv[(size_t)T_TOK * 320];       // fused down-proj out (f32)
__device__ float  g_krope[T_TOK * KROPE];
__device__ __half g_qrawh[(size_t)T_TOK * 1024];
__device__ __half g_kvrawh[(size_t)T_TOK * 2560];
__device__ __half g_xh[(size_t)T_TOK * DIMM];
__device__ __half g_wqkv[DIMM * 320];                // packed [k][wdq(128) | wdkv(192)]
__device__ float  g_bqkv[320];
__device__ __half g_wuq[QC * 1024];
__device__ __half g_wuk[KVC * 2560];
__device__ __half g_wo[(size_t)2048 * DIMM];
__device__ __half g_cqh[T_TOK * QC];
__device__ __half g_ckvh[T_TOK * KVC];
__device__ __half g_qh[(size_t)16 * S_LEN * HD];     // [bh][s][128]
__device__ __half g_kh[(size_t)16 * S_LEN * HD];     // [bh][s][128]
__device__ __half g_vth[(size_t)16 * VHD * S_LEN];   // [bh][n][s] (V^T)
__device__ __half g_attnh[(size_t)T_TOK * 2048];

// ---------------- helpers ----------------
__device__ __forceinline__ void mma_f16(float c[4], const uint32_t a[4], const uint32_t b[2]) {
    asm volatile(
        "mma.sync.aligned.m16n8k16.row.col.f32.f16.f16.f32 "
        "{%0,%1,%2,%3},{%4,%5,%6,%7},{%8,%9},{%0,%1,%2,%3};"
        : "+f"(c[0]), "+f"(c[1]), "+f"(c[2]), "+f"(c[3])
        : "r"(a[0]), "r"(a[1]), "r"(a[2]), "r"(a[3]), "r"(b[0]), "r"(b[1]));
}

__device__ __forceinline__ void ldsm4(uint32_t r[4], uint32_t saddr) {
    asm volatile("ldmatrix.sync.aligned.m8n8.x4.shared.b16 {%0,%1,%2,%3}, [%4];"
        : "=r"(r[0]), "=r"(r[1]), "=r"(r[2]), "=r"(r[3]) : "r"(saddr));
}
__device__ __forceinline__ void ldsm4t(uint32_t r[4], uint32_t saddr) {
    asm volatile("ldmatrix.sync.aligned.m8n8.x4.trans.shared.b16 {%0,%1,%2,%3}, [%4];"
        : "=r"(r[0]), "=r"(r[1]), "=r"(r[2]), "=r"(r[3]) : "r"(saddr));
}

__device__ __forceinline__ void cp_async16(void* smem_dst, const void* gsrc) {
    uint32_t s = (uint32_t)__cvta_generic_to_shared(smem_dst);
    asm volatile("cp.async.ca.shared.global [%0], [%1], 16;\n" :: "r"(s), "l"(gsrc));
}
#define CP_COMMIT() asm volatile("cp.async.commit_group;\n" ::: "memory")
#define CP_WAIT1()  asm volatile("cp.async.wait_group 1;\n" ::: "memory")

__device__ __forceinline__ uint32_t packh2(float lo, float hi) {
    __half2 h = __floats2half2_rn(lo, hi);
    return *(uint32_t*)&h;
}

// ---------------- fused f32 -> f16 conversion (x + all weights, packed down-proj) ----
#define CV_X   (T_TOK * DIMM)            // 4194304
#define CV_DQ  (DIMM * QC)               // 131072
#define CV_DKV (DIMM * 192)              // 196608
#define CV_UQ  (QC * 1024)               // 131072
#define CV_UK  (KVC * 2560)              // 327680
#define CV_WO  (2048 * DIMM)             // 2097152
#define CV_TOTAL (CV_X + CV_DQ + CV_DKV + CV_UQ + CV_UK + CV_WO)
#define CV_QUADS (CV_TOTAL / 4)

__global__ __launch_bounds__(256) void convert_all(
    const float* __restrict__ x,   const float* __restrict__ wdq,
    const float* __restrict__ wdkv,const float* __restrict__ wuq,
    const float* __restrict__ wuk, const float* __restrict__ wo,
    const float* __restrict__ bdq, const float* __restrict__ bdkv,
    __half* __restrict__ xh,   __half* __restrict__ wqkvh,
    __half* __restrict__ wuqh, __half* __restrict__ wukh,
    __half* __restrict__ woh,  float* __restrict__ bqkv)
{
    if (blockIdx.x == 0) {
        int tix = threadIdx.x;
        if (tix < 320) bqkv[tix] = (tix < 128) ? bdq[tix] : bdkv[tix - 128];
        if (tix < 64)  bqkv[256 + tix] = bdkv[128 + tix];
    }
    long long i = ((long long)blockIdx.x * 256 + threadIdx.x) * 4;
    if (i >= CV_TOTAL) return;
    long long off = i;
    const float* src;
    __half* dst;
    long long didx;
    if (off < CV_X) {
        src = x; dst = xh; didx = off;
    } else if ((off -= CV_X) < CV_DQ) {
        src = wdq; dst = wqkvh;
        didx = (off >> 7) * 320 + (off & 127);
    } else if ((off -= CV_DQ) < CV_DKV) {
        src = wdkv; dst = wqkvh;
        didx = (off / 192) * 320 + 128 + (off % 192);
    } else if ((off -= CV_DKV) < CV_UQ) {
        src = wuq; dst = wuqh; didx = off;
    } else if ((off -= CV_UQ) < CV_UK) {
        src = wuk; dst = wukh; didx = off;
    } else {
        off -= CV_UK; src = wo; dst = woh; didx = off;
    }
    float4 v = *(const float4*)&src[off];
    *(__half2*)&dst[didx]     = __floats2half2_rn(v.x, v.y);
    *(__half2*)&dst[didx + 2] = __floats2half2_rn(v.z, v.w);
}

// ---------------- fp16 tensor-core GEMM, 3-stage cp.async pipeline ----------------
template<int BN, bool HALF_OUT>
__global__ __launch_bounds__(256, 2) void hgemm(
    const __half* __restrict__ A, const __half* __restrict__ W,
    const float* __restrict__ bias, void* __restrict__ Cv,
    int M, int N, int K)
{
    constexpr int BM = 128, BK = 32, ST = 3;
    constexpr int LDA = BK + 8;
    constexpr int LDB = BN + 8;
    constexpr int WN = BN / 2;
    constexpr int NB = WN / 8;
    constexpr int NB16 = WN / 16;
    __shared__ __half As[ST][BM][LDA];
    __shared__ __half Bs[ST][BK][LDB];

    int tid = threadIdx.x, lane = tid & 31, w = tid >> 5;
    int g = lane >> 2, t = lane & 3;
    int wm = (w >> 1) * 32, wn = (w & 1) * WN;
    int m0 = blockIdx.y * BM, n0 = blockIdx.x * BN;

    int rowX = (lane & 7) + ((lane >> 3) & 1) * 8;
    int colX = (lane >> 4) * 8;

    uint32_t aAddr = (uint32_t)__cvta_generic_to_shared(&As[0][wm + rowX][colX]);
    uint32_t bAddr = (uint32_t)__cvta_generic_to_shared(&Bs[0][rowX][wn + colX]);
    constexpr uint32_t ABUF = BM * LDA * 2;
    constexpr uint32_t BBUF = BK * LDB * 2;

    const __half* Ag = A + (size_t)m0 * K;
    const __half* Wg = W + n0;

    auto load = [&](int k0, int buf) {
        #pragma unroll
        for (int i = tid; i < BM * BK / 8; i += 256) {
            int r = i >> 2, c = (i & 3) * 8;
            cp_async16(&As[buf][r][c], &Ag[(size_t)r * K + k0 + c]);
        }
        #pragma unroll
        for (int i = tid; i < BK * BN / 8; i += 256) {
            int r = i / (BN / 8), c = (i % (BN / 8)) * 8;
            cp_async16(&Bs[buf][r][c], &Wg[(size_t)(k0 + r) * N + c]);
        }
    };

    float c[2][NB][4] = {};

    int nt = K / BK;
    load(0, 0); CP_COMMIT();
    load(BK, 1); CP_COMMIT();

    for (int it = 0; it < nt; it++) {
        int buf = it % 3;
        CP_WAIT1();
        __syncthreads();
        if (it + 2 < nt) load((it + 2) * BK, (it + 2) % 3);
        CP_COMMIT();

        uint32_t af[2][2][4];
        #pragma unroll
        for (int i = 0; i < 2; i++)
            #pragma unroll
            for (int kg = 0; kg < 2; kg++)
                ldsm4(af[i][kg], aAddr + buf * ABUF + (i * 16 * LDA + kg * 16) * 2);

        #pragma unroll
        for (int kg = 0; kg < 2; kg++) {
            #pragma unroll
            for (int nb = 0; nb < NB16; nb++) {
                uint32_t bb[4];
                ldsm4t(bb, bAddr + buf * BBUF + (kg * 16 * LDB + nb * 16) * 2);
                #pragma unroll
                for (int i = 0; i < 2; i++) {
                    mma_f16(c[i][2 * nb],     af[i][kg], &bb[0]);
                    mma_f16(c[i][2 * nb + 1], af[i][kg], &bb[2]);
                }
            }
        }
    }

    #pragma unroll
    for (int i = 0; i < 2; i++) {
        #pragma unroll
        for (int nb = 0; nb < NB; nb++) {
            int row = m0 + wm + i * 16 + g;
            int col = n0 + wn + nb * 8 + 2 * t;
            float2 bb2 = *(const float2*)&bias[col];
            float o00 = c[i][nb][0] + bb2.x, o01 = c[i][nb][1] + bb2.y;
            float o10 = c[i][nb][2] + bb2.x, o11 = c[i][nb][3] + bb2.y;
            if (HALF_OUT) {
                __half* C = (__half*)Cv;
                *(uint32_t*)&C[(size_t)row * N + col] = packh2(o00, o01);
                *(uint32_t*)&C[(size_t)(row + 8) * N + col] = packh2(o10, o11);
            } else {
                float* C = (float*)Cv;
                float2 v0 = { o00, o01 }, v1 = { o10, o11 };
                *(float2*)&C[(size_t)row * N + col] = v0;
                *(float2*)&C[(size_t)(row + 8) * N + col] = v1;
            }
        }
    }
}

// ---------------- fused RMSNorm + K-rope (fp32 rope, no DP) ----------------
__global__ __launch_bounds__(128) void norm_rope_kernel(
    const float* __restrict__ dqkv,
    const float* __restrict__ qnw, const float* __restrict__ kvnw,
    const int* __restrict__ pos_ids,
    __half* __restrict__ cq, __half* __restrict__ ckv, float* __restrict__ kr)
{
    int t = blockIdx.x, tid = threadIdx.x;
    int lane = tid & 31, wid = tid >> 5;
    __shared__ float r1[4], r2[4];
    const float* row = dqkv + (size_t)t * 320;
    float v1 = row[tid];
    float v2 = row[128 + tid];
    float s1 = v1 * v1, s2 = v2 * v2;
    #pragma unroll
    for (int o = 16; o; o >>= 1) {
        s1 += __shfl_xor_sync(0xffffffffu, s1, o);
        s2 += __shfl_xor_sync(0xffffffffu, s2, o);
    }
    if (!lane) { r1[wid] = s1; r2[wid] = s2; }
    __syncthreads();
    float t1 = r1[0] + r1[1] + r1[2] + r1[3];
    float t2 = r2[0] + r2[1] + r2[2] + r2[3];
    cq[t * 128 + tid]  = __float2half_rn(qnw[tid]  * v1 * rsqrtf(t1 * (1.0f / 128.0f) + 1e-8f));
    ckv[t * 128 + tid] = __float2half_rn(kvnw[tid] * v2 * rsqrtf(t2 * (1.0f / 128.0f) + 1e-8f));
    if (tid < 64) {
        int p = pos_ids[t];
        int i = tid >> 1;
        float invf = exp2f(-(float)i * KR_EXP);
        float ang = (float)p * invf;
        float sn, cs; sincosf(ang, &sn, &cs);
        float xe = row[256 + 2 * i];
        float xo = row[256 + 2 * i + 1];
        kr[t * 64 + tid] = (tid & 1) ? (xe * sn + xo * cs) : (xe * cs - xo * sn);
    }
}

// ---------------- scatter Q/K (trig hoisted out of head loop) ----------------
__global__ __launch_bounds__(256) void scatter_qk(
    const __half* __restrict__ qraw, const __half* __restrict__ kvraw,
    const float* __restrict__ kr, const int* __restrict__ pos_ids,
    __half* __restrict__ gq, __half* __restrict__ gk)
{
    int t = blockIdx.x;
    int b = t >> 11, s = t & 2047;
    int tid = threadIdx.x;
    int p = pos_ids[t];
    const __half* qrow = qraw + (size_t)t * 1024;
    const __half* kvrow = kvraw + (size_t)t * 2560;

    float sn = 0.f, cs = 0.f;
    int j = 0, iq = 0;
    if (tid >= 96 && tid < 128) {
        j = tid - 96; iq = j >> 1;
        float invf = exp2f(-(float)iq * QR_EXP);
        float ang = (float)p * invf;
        sincosf(ang, &sn, &cs);
    }

    for (int h = 0; h < 8; h++) {
        size_t qk_base = ((size_t)(b * 8 + h) * 2048 + s) * 128;
        if (tid < 128) {
            int d = tid;
            __half val;
            if (d < 96) {
                val = qrow[h * 96 + d];
            } else {
                const __half* rb = qrow + 768 + h * 32;
                float xe = __half2float(rb[2 * iq]), xo = __half2float(rb[2 * iq + 1]);
                val = __float2half_rn((j & 1) ? (xe * sn + xo * cs) : (xe * cs - xo * sn));
            }
            gq[qk_base + d] = val;
        } else {
            int d = tid - 128;
            gk[qk_base + d] = (d < 64) ? kvrow[h * 64 + d]
                                       : __float2half_rn(kr[t * 64 + (d - 64)]);
        }
    }
}

// ---------------- V transpose (fp16 in) -> fp16 [bh][n][s] ----------------
__global__ __launch_bounds__(256) void v_transpose(
    const __half* __restrict__ kvraw, __half* __restrict__ gvt)
{
    __shared__ __half ts[32][36];
    int bh = blockIdx.x;
    int s0 = blockIdx.y * 32, n0 = blockIdx.z * 32;
    int b = bh >> 3, h = bh & 7;
    int c = threadIdx.x & 31, r0 = threadIdx.x >> 5;
    #pragma unroll
    for (int rr = r0; rr < 32; rr += 8)
        ts[rr][c] = kvraw[(size_t)(b * 2048 + s0 + rr) * 2560 + 512 + h * 256 + n0 + c];
    __syncthreads();
    #pragma unroll
    for (int rr = r0; rr < 32; rr += 8)
        gvt[(size_t)(bh * 256 + n0 + rr) * 2048 + s0 + c] = ts[c][rr];
}

// ---------------- fp16 flash attention (unchanged from round 9) ----------------
#define LQ 136
#define LK 136
#define LV 72
#define FQ_H (128 * LQ)
#define FK_H (64 * LK)
#define FV_H (256 * LV)
#define FA5_BYTES ((FQ_H + FK_H + FV_H) * 2 + 256)

__global__ __launch_bounds__(256, 1) void flash_f16(
    const __half* __restrict__ Q, const __half* __restrict__ K,
    const __half* __restrict__ VT, __half* __restrict__ O)
{
    extern __shared__ __align__(16) __half smh[];
    __half* Qs = smh;            // [128][136]
    __half* Ks = Qs + FQ_H;      // [64][136]
    __half* Vs = Ks + FK_H;      // [256][72]

    int bh = blockIdx.y, q0 = blockIdx.x * 128;
    const __half* Qg = Q + ((size_t)bh * 2048 + q0) * 128;
    const __half* Kg = K + (size_t)bh * 2048 * 128;
    const __half* Vg = VT + (size_t)bh * 256 * 2048;
    int tid = threadIdx.x, lane = tid & 31, w = tid >> 5;
    int g = lane >> 2, t = lane & 3;
    int wm = w * 16;

    int rowA = (lane & 7) + ((lane >> 3) & 1) * 8;
    int colA = (lane >> 4) * 8;
    int rowB = (lane & 7) + ((lane >> 4) & 1) * 8;
    int colB = ((lane >> 3) & 1) * 8;

    uint32_t qA = (uint32_t)__cvta_generic_to_shared(&Qs[(wm + rowA) * LQ + colA]);
    uint32_t kB = (uint32_t)__cvta_generic_to_shared(&Ks[rowB * LK + colB]);
    uint32_t vB = (uint32_t)__cvta_generic_to_shared(&Vs[rowB * LV + colB]);

    auto loadK = [&](int kc) {
        const __half* Kc = Kg + (size_t)kc * 64 * 128;
        #pragma unroll
        for (int i = tid; i < 1024; i += 256) {
            int r = i >> 4, c = i & 15;
            cp_async16(&Ks[r * LK + c * 8], &Kc[r * 128 + c * 8]);
        }
    };
    auto loadV = [&](int kc) {
        #pragma unroll
        for (int i = tid; i < 2048; i += 256) {
            int r = i >> 3, c = i & 7;
            cp_async16(&Vs[r * LV + c * 8], &Vg[(size_t)r * 2048 + kc * 64 + c * 8]);
        }
    };

    for (int i = tid; i < 2048; i += 256) {
        int r = i >> 4, c = i & 15;
        *(uint4*)&Qs[r * LQ + c * 8] = *(const uint4*)&Qg[r * 128 + c * 8];
    }
    loadK(0); CP_COMMIT();
    loadV(0); CP_COMMIT();
    __syncthreads();

    uint32_t qf[8][4];
    #pragma unroll
    for (int kg = 0; kg < 8; kg++) ldsm4(qf[kg], qA + kg * 32);

    float m0 = -1e30f, m1 = -1e30f, l0 = 0.f, l1 = 0.f;
    float oc[32][4] = {};
    const float scale = 0.08838834764831845f;  // 1/sqrt(128)

    for (int kc = 0; kc < 32; kc++) {
        CP_WAIT1();
        __syncthreads();

        float sc[8][4] = {};
        #pragma unroll
        for (int kg = 0; kg < 8; kg++) {
            #pragma unroll
            for (int ng = 0; ng < 4; ng++) {
                uint32_t bb[4];
                ldsm4(bb, kB + ng * 16 * LK * 2 + kg * 32);
                mma_f16(sc[2 * ng],     qf[kg], &bb[0]);
                mma_f16(sc[2 * ng + 1], qf[kg], &bb[2]);
            }
        }
        __syncthreads();

        float mc0 = -1e30f, mc1 = -1e30f;
        #pragma unroll
        for (int jj = 0; jj < 8; jj++) {
            sc[jj][0] *= scale; sc[jj][1] *= scale;
            sc[jj][2] *= scale; sc[jj][3] *= scale;
            mc0 = fmaxf(mc0, fmaxf(sc[jj][0], sc[jj][1]));
            mc1 = fmaxf(mc1, fmaxf(sc[jj][2], sc[jj][3]));
        }
        mc0 = fmaxf(mc0, __shfl_xor_sync(0xffffffffu, mc0, 1));
        mc0 = fmaxf(mc0, __shfl_xor_sync(0xffffffffu, mc0, 2));
        mc1 = fmaxf(mc1, __shfl_xor_sync(0xffffffffu, mc1, 1));
        mc1 = fmaxf(mc1, __shfl_xor_sync(0xffffffffu, mc1, 2));
        float mn0 = fmaxf(m0, mc0), mn1 = fmaxf(m1, mc1);
        float al0 = __expf(m0 - mn0), al1 = __expf(m1 - mn1);
        m0 = mn0; m1 = mn1;

        uint32_t ph[4][4];
        float ls0 = 0.f, ls1 = 0.f;
        #pragma unroll
        for (int jj = 0; jj < 8; jj++) {
            float e0 = __expf(sc[jj][0] - mn0);
            float e1 = __expf(sc[jj][1] - mn0);
            float e2 = __expf(sc[jj][2] - mn1);
            float e3 = __expf(sc[jj][3] - mn1);
            ls0 += e0 + e1; ls1 += e2 + e3;
            int kg = jj >> 1, hi = (jj & 1) * 2;
            ph[kg][hi]     = packh2(e0, e1);
            ph[kg][hi + 1] = packh2(e2, e3);
        }
        ls0 += __shfl_xor_sync(0xffffffffu, ls0, 1);
        ls0 += __shfl_xor_sync(0xffffffffu, ls0, 2);
        ls1 += __shfl_xor_sync(0xffffffffu, ls1, 1);
        ls1 += __shfl_xor_sync(0xffffffffu, ls1, 2);
        l0 = l0 * al0 + ls0;
        l1 = l1 * al1 + ls1;

        if (kc + 1 < 32) loadK(kc + 1);
        CP_COMMIT();
        CP_WAIT1();
        __syncthreads();

        #pragma unroll
        for (int nt = 0; nt < 32; nt++) {
            oc[nt][0] *= al0; oc[nt][1] *= al0;
            oc[nt][2] *= al1; oc[nt][3] *= al1;
        }
        #pragma unroll
        for (int kg = 0; kg < 4; kg++) {
            #pragma unroll
            for (int ng = 0; ng < 16; ng++) {
                uint32_t bb[4];
                ldsm4(bb, vB + ng * 16 * LV * 2 + kg * 32);
                mma_f16(oc[2 * ng],     ph[kg], &bb[0]);
                mma_f16(oc[2 * ng + 1], ph[kg], &bb[2]);
            }
        }
        __syncthreads();
        if (kc + 1 < 32) loadV(kc + 1);
        CP_COMMIT();
    }

    int b = bh >> 3, h = bh & 7;
    float inv0 = 1.0f / l0, inv1 = 1.0f / l1;
    int row0 = q0 + wm + g, row1 = row0 + 8;
    #pragma unroll
    for (int nt = 0; nt < 32; nt++) {
        int col = h * 256 + nt * 8 + 2 * t;
        uint32_t p0 = packh2(oc[nt][0] * inv0, oc[nt][1] * inv0);
        uint32_t p1 = packh2(oc[nt][2] * inv1, oc[nt][3] * inv1);
        *(uint32_t*)&O[((size_t)(b * 2048 + row0)) * 2048 + col] = p0;
        *(uint32_t*)&O[((size_t)(b * 2048 + row1)) * 2048 + col] = p1;
    }
}

// ---------------- launch ----------------
extern "C" void kernel_launch(void* const* d_in, const int* in_sizes, int n_in,
                              void* d_out, int out_size)
{
    const float* x         = (const float*)d_in[0];
    const int*   pos       = (const int*)d_in[1];
    const float* w_dq_w    = (const float*)d_in[2];
    const float* w_dq_b    = (const float*)d_in[3];
    const float* q_norm_w  = (const float*)d_in[4];
    const float* w_uq_qr_w = (const float*)d_in[5];
    const float* w_uq_qr_b = (const float*)d_in[6];
    const float* w_dkv_w   = (const float*)d_in[7];
    const float* w_dkv_b   = (const float*)d_in[8];
    const float* kv_norm_w = (const float*)d_in[9];
    const float* w_uk_w    = (const float*)d_in[10];
    const float* w_uk_b    = (const float*)d_in[11];
    const float* w_o_w     = (const float*)d_in[12];
    const float* w_o_b     = (const float*)d_in[13];
    float* out = (float*)d_out;

    float *dqkv, *kr, *bqkv;
    __half *xh, *wqkv, *wuq, *wuk, *wo, *cqh, *ckvh;
    __half *qrawh, *kvrawh, *gq, *gk, *gvt, *attnh;
    cudaGetSymbolAddress((void**)&dqkv, g_dqkv);
    cudaGetSymbolAddress((void**)&kr, g_krope);
    cudaGetSymbolAddress((void**)&bqkv, g_bqkv);
    cudaGetSymbolAddress((void**)&qrawh, g_qrawh);
    cudaGetSymbolAddress((void**)&kvrawh, g_kvrawh);
    cudaGetSymbolAddress((void**)&xh, g_xh);
    cudaGetSymbolAddress((void**)&wqkv, g_wqkv);
    cudaGetSymbolAddress((void**)&wuq, g_wuq);
    cudaGetSymbolAddress((void**)&wuk, g_wuk);
    cudaGetSymbolAddress((void**)&wo, g_wo);
    cudaGetSymbolAddress((void**)&cqh, g_cqh);
    cudaGetSymbolAddress((void**)&ckvh, g_ckvh);
    cudaGetSymbolAddress((void**)&gq, g_qh);
    cudaGetSymbolAddress((void**)&gk, g_kh);
    cudaGetSymbolAddress((void**)&gvt, g_vth);
    cudaGetSymbolAddress((void**)&attnh, g_attnh);

    cudaFuncSetAttribute(flash_f16, cudaFuncAttributeMaxDynamicSharedMemorySize,
                         FA5_BYTES);

    // fused fp16 conversion + weight packing + bias packing
    convert_all<<<(CV_QUADS + 255) / 256, 256>>>(
        x, w_dq_w, w_dkv_w, w_uq_qr_w, w_uk_w, w_o_w, w_dq_b, w_dkv_b,
        xh, wqkv, wuq, wuk, wo, bqkv);

    // fused down projection (N=320: [dq | dkv])
    hgemm<64, false><<<dim3(5, 32), 256>>>(xh, wqkv, bqkv, dqkv, T_TOK, 320, DIMM);
    // rmsnorm + k rope
    norm_rope_kernel<<<T_TOK, 128>>>(dqkv, q_norm_w, kv_norm_w, pos, cqh, ckvh, kr);
    // up projections (fp16 out)
    hgemm<128, true><<<dim3(8, 32), 256>>>(cqh, wuq, w_uq_qr_b, qrawh, T_TOK, 1024, QC);
    hgemm<128, true><<<dim3(20, 32), 256>>>(ckvh, wuk, w_uk_b, kvrawh, T_TOK, 2560, KVC);
    // build per-head states
    scatter_qk<<<T_TOK, 256>>>(qrawh, kvrawh, kr, pos, gq, gk);
    v_transpose<<<dim3(16, 64, 8), 256>>>(kvrawh, gvt);
    // attention
    flash_f16<<<dim3(S_LEN / 128, 16), 256, FA5_BYTES>>>(gq, gk, gvt, attnh);
    // output projection (fp32 out)
    hgemm<128, false><<<dim3(8, 32), 256>>>(attnh, wo, w_o_b, out, T_TOK, DIMM, 2048);
}